// round 8
// baseline (speedup 1.0000x reference)
#include <cuda_runtime.h>
#include <cuda_bf16.h>
#include <math.h>
#include <stdint.h>

#define NN   50000
#define EE   800000
#define DIN  128
#define D1   150
#define KP1  160     // h1 K-padded (5 chunks of 32)
#define D2   100
#define KP2  128     // h2 K-padded
#define DOUT 64
#define SCAN_B ((NN + 1023) / 1024)

// ---------------- scratch ----------------
__device__ float g_deg_out[NN];
__device__ int   g_deg_in[NN];
__device__ int   g_off[NN + 1];
__device__ int   g_cur[NN];
__device__ int   g_pref[SCAN_B];
__device__ int   g_csr[EE];
__device__ float g_norm_out[NN];
__device__ float g_norm_in[NN];
__device__ float g_invdeg[NN];

__device__ __align__(16) __nv_bfloat16 g_aggh[(size_t)NN * DIN];
__device__ __align__(16) __nv_bfloat16 g_aggl[(size_t)NN * DIN];
__device__ __align__(16) __nv_bfloat16 g_h1h[(size_t)NN * KP1];
__device__ __align__(16) __nv_bfloat16 g_h1l[(size_t)NN * KP1];
__device__ __align__(16) __nv_bfloat16 g_h2h[(size_t)NN * KP2];
__device__ __align__(16) __nv_bfloat16 g_h2l[(size_t)NN * KP2];
__device__ __align__(16) float g_hWn[(size_t)NN * D2];    // h1 @ Wn
__device__ __align__(16) float g_h2pre[(size_t)NN * D2];  // h1 @ Ws + b2

// weights transposed [NPAD, KPAD] bf16 hi/lo
__device__ __align__(16) __nv_bfloat16 g_B1h[160 * 128],  g_B1l[160 * 128];
__device__ __align__(16) __nv_bfloat16 g_BWmh[256 * 160], g_BWml[256 * 160]; // [Wn|Ws]
__device__ __align__(16) __nv_bfloat16 g_B3h[64 * 128],   g_B3l[64 * 128];
__device__ float g_bias_m[256];   // 0 for c<100, b2[c-100] for 100..199, 0 after

__device__ __forceinline__ float elu_f(float v) { return v > 0.f ? v : expm1f(v); }

__device__ __forceinline__ uint32_t smem_u32(const void* p) {
    uint32_t a;
    asm("{ .reg .u64 t; cvta.to.shared.u64 t, %1; cvt.u32.u64 %0, t; }" : "=r"(a) : "l"(p));
    return a;
}
__device__ __forceinline__ void ldsm_x4(uint32_t addr, uint32_t* r) {
    asm volatile("ldmatrix.sync.aligned.m8n8.x4.shared.b16 {%0,%1,%2,%3}, [%4];"
                 : "=r"(r[0]), "=r"(r[1]), "=r"(r[2]), "=r"(r[3]) : "r"(addr));
}
__device__ __forceinline__ void mma_bf16(float* d, const uint32_t* a, const uint32_t* b) {
    asm volatile("mma.sync.aligned.m16n8k16.row.col.f32.bf16.bf16.f32 "
                 "{%0,%1,%2,%3}, {%4,%5,%6,%7}, {%8,%9}, {%0,%1,%2,%3};"
                 : "+f"(d[0]), "+f"(d[1]), "+f"(d[2]), "+f"(d[3])
                 : "r"(a[0]), "r"(a[1]), "r"(a[2]), "r"(a[3]), "r"(b[0]), "r"(b[1]));
}

// ---------------- preprocessing (scalar: max TLP hides atomic latency) ----------
__global__ void k_zero() {
    int i = blockIdx.x * blockDim.x + threadIdx.x;
    if (i < NN) { g_deg_out[i] = 0.f; g_deg_in[i] = 0; g_cur[i] = 0; }
    if (i < SCAN_B) g_pref[i] = 0;
}
__global__ void k_degrees(const int* __restrict__ src, const int* __restrict__ dst) {
    int e = blockIdx.x * blockDim.x + threadIdx.x;
    if (e >= EE) return;
    atomicAdd(&g_deg_out[src[e]], 1.f);
    atomicAdd(&g_deg_in[dst[e]], 1);
}
__global__ void k_scan_norms() {
    __shared__ int s[1024];
    __shared__ int s_carry;
    int tid = threadIdx.x, b = blockIdx.x;
    int i = b * 1024 + tid;
    if (i < NN) {
        g_norm_out[i] = rsqrtf(fmaxf(g_deg_out[i], 1.f));
        float dmx = fmaxf((float)g_deg_in[i], 1.f);
        g_norm_in[i] = rsqrtf(dmx);
        g_invdeg[i]  = 1.f / dmx;
    }
    int v = (i < NN) ? g_deg_in[i] : 0;
    s[tid] = v;
    __syncthreads();
    for (int off = 1; off < 1024; off <<= 1) {
        int t = (tid >= off) ? s[tid - off] : 0;
        __syncthreads();
        s[tid] += t;
        __syncthreads();
    }
    if (tid == 1023) {
        int prev = 0;
        if (b > 0) {
            int pv;
            do { pv = atomicAdd(&g_pref[b - 1], 0); } while (pv == 0);
            prev = pv - 1;
        }
        atomicExch(&g_pref[b], prev + s[1023] + 1);
        s_carry = prev;
    }
    __syncthreads();
    int carry = s_carry;
    if (i < NN) g_off[i + 1] = s[tid] + carry;
    if (i == 0) g_off[0] = 0;
}
__global__ void k_fill(const int* __restrict__ src, const int* __restrict__ dst) {
    int e = blockIdx.x * blockDim.x + threadIdx.x;
    if (e >= EE) return;
    int d = dst[e];
    int p = atomicAdd(&g_cur[d], 1);
    g_csr[g_off[d] + p] = src[e];
}

// ---------------- fused weight prep ----------------
__device__ __forceinline__ void wsplit(const float* W, int KB, int NB, int KPAD,
                                       __nv_bfloat16* bh, __nv_bfloat16* bl, int idx) {
    int n = idx / KPAD, k = idx % KPAD;
    float v = (n < NB && k < KB) ? W[(size_t)k * NB + n] : 0.f;
    __nv_bfloat16 hv = __float2bfloat16(v);
    bh[idx] = hv;
    bl[idx] = __float2bfloat16(v - __bfloat162float(hv));
}
__global__ void k_wprep_all(const float* __restrict__ W1, const float* __restrict__ Wn,
                            const float* __restrict__ Ws, const float* __restrict__ W3,
                            const float* __restrict__ b2) {
    int i = blockIdx.x * 256 + threadIdx.x;
    const int S1 = 160 * 128, S2 = 256 * 160, S4 = 64 * 128;
    if (i < S1) { wsplit(W1, DIN, D1, 128, g_B1h, g_B1l, i); return; }
    i -= S1;
    if (i < S2) {  // merged [Wn rows 0..99 | Ws rows 100..199 | zeros]
        int n = i / 160, k = i % 160;
        float v = 0.f;
        if (n < 100 && k < D1)            v = Wn[(size_t)k * D2 + n];
        else if (n >= 100 && n < 200 && k < D1) v = Ws[(size_t)k * D2 + (n - 100)];
        __nv_bfloat16 hv = __float2bfloat16(v);
        g_BWmh[i] = hv;
        g_BWml[i] = __float2bfloat16(v - __bfloat162float(hv));
        return;
    }
    i -= S2;
    if (i < S4) { wsplit(W3, D2, DOUT, 128, g_B3h, g_B3l, i); return; }
    i -= S4;
    if (i < 256) g_bias_m[i] = (i >= 100 && i < 200) ? b2[i - 100] : 0.f;
}

// ---------------- layer-1 aggregation -> bf16 hi/lo ----------------
__global__ void k_agg1(const float* __restrict__ x) {
    int w    = (blockIdx.x * blockDim.x + threadIdx.x) >> 5;
    int lane = threadIdx.x & 31;
    if (w >= NN) return;
    int beg = g_off[w], end = g_off[w + 1];
    const float4* X = (const float4*)x;
    float4 acc = make_float4(0.f, 0.f, 0.f, 0.f);
    int j = beg;
    for (; j + 3 < end; j += 4) {
        int s0 = g_csr[j], s1 = g_csr[j + 1], s2 = g_csr[j + 2], s3 = g_csr[j + 3];
        float w0 = g_norm_out[s0], w1 = g_norm_out[s1];
        float w2 = g_norm_out[s2], w3 = g_norm_out[s3];
        float4 v0 = X[(size_t)s0 * 32 + lane];
        float4 v1 = X[(size_t)s1 * 32 + lane];
        float4 v2 = X[(size_t)s2 * 32 + lane];
        float4 v3 = X[(size_t)s3 * 32 + lane];
        acc.x += v0.x * w0 + v1.x * w1 + v2.x * w2 + v3.x * w3;
        acc.y += v0.y * w0 + v1.y * w1 + v2.y * w2 + v3.y * w3;
        acc.z += v0.z * w0 + v1.z * w1 + v2.z * w2 + v3.z * w3;
        acc.w += v0.w * w0 + v1.w * w1 + v2.w * w2 + v3.w * w3;
    }
    for (; j < end; j++) {
        int s0 = g_csr[j];
        float w0 = g_norm_out[s0];
        float4 v0 = X[(size_t)s0 * 32 + lane];
        acc.x += v0.x * w0; acc.y += v0.y * w0; acc.z += v0.z * w0; acc.w += v0.w * w0;
    }
    float ni = g_norm_in[w];
    float v[4] = { acc.x * ni, acc.y * ni, acc.z * ni, acc.w * ni };
    __nv_bfloat16 hv[4], lv[4];
#pragma unroll
    for (int q = 0; q < 4; q++) {
        hv[q] = __float2bfloat16(v[q]);
        lv[q] = __float2bfloat16(v[q] - __bfloat162float(hv[q]));
    }
    *(ushort4*)&g_aggh[(size_t)w * DIN + lane * 4] =
        make_ushort4(__bfloat16_as_ushort(hv[0]), __bfloat16_as_ushort(hv[1]),
                     __bfloat16_as_ushort(hv[2]), __bfloat16_as_ushort(hv[3]));
    *(ushort4*)&g_aggl[(size_t)w * DIN + lane * 4] =
        make_ushort4(__bfloat16_as_ushort(lv[0]), __bfloat16_as_ushort(lv[1]),
                     __bfloat16_as_ushort(lv[2]), __bfloat16_as_ushort(lv[3]));
}

// ---------------- fused SAGE tail: h2 = elu(h2pre + mean-agg(hWn)) -> bf16 -------
__global__ void k_agg2p() {
    int w    = (blockIdx.x * blockDim.x + threadIdx.x) >> 5;
    int lane = threadIdx.x & 31;
    if (w >= NN) return;
    float4 acc = make_float4(0.f, 0.f, 0.f, 0.f);
    if (lane < D2 / 4) {
        int beg = g_off[w], end = g_off[w + 1];
        const float4* X = (const float4*)g_hWn;
        int j = beg;
        for (; j + 1 < end; j += 2) {
            int s0 = g_csr[j], s1 = g_csr[j + 1];
            float4 v0 = X[(size_t)s0 * (D2 / 4) + lane];
            float4 v1 = X[(size_t)s1 * (D2 / 4) + lane];
            acc.x += v0.x + v1.x; acc.y += v0.y + v1.y;
            acc.z += v0.z + v1.z; acc.w += v0.w + v1.w;
        }
        if (j < end) {
            int s0 = g_csr[j];
            float4 v0 = X[(size_t)s0 * (D2 / 4) + lane];
            acc.x += v0.x; acc.y += v0.y; acc.z += v0.z; acc.w += v0.w;
        }
        float inv = g_invdeg[w];
        float4 p = ((const float4*)g_h2pre)[(size_t)w * (D2 / 4) + lane];
        acc.x = elu_f(p.x + acc.x * inv);
        acc.y = elu_f(p.y + acc.y * inv);
        acc.z = elu_f(p.z + acc.z * inv);
        acc.w = elu_f(p.w + acc.w * inv);
    } else {
        acc = make_float4(0.f, 0.f, 0.f, 0.f);   // K-pad cols 100..127
    }
    float v[4] = { acc.x, acc.y, acc.z, acc.w };
    __nv_bfloat16 hv[4], lv[4];
#pragma unroll
    for (int q = 0; q < 4; q++) {
        hv[q] = __float2bfloat16(v[q]);
        lv[q] = __float2bfloat16(v[q] - __bfloat162float(hv[q]));
    }
    *(ushort4*)&g_h2h[(size_t)w * KP2 + lane * 4] =
        make_ushort4(__bfloat16_as_ushort(hv[0]), __bfloat16_as_ushort(hv[1]),
                     __bfloat16_as_ushort(hv[2]), __bfloat16_as_ushort(hv[3]));
    *(ushort4*)&g_h2l[(size_t)w * KP2 + lane * 4] =
        make_ushort4(__bfloat16_as_ushort(lv[0]), __bfloat16_as_ushort(lv[1]),
                     __bfloat16_as_ushort(lv[2]), __bfloat16_as_ushort(lv[3]));
}

// ---------------- fused 3-term bf16-split GEMM with frag skipping ----------------
// OUTM: 0 = fp32 single, 1 = bf16 hi/lo split, 2 = dual fp32 (c<100 -> Of, else Og)
template<int NWN, int KPAD, int OUTM, bool HAS_ELU, int MINB>
__global__ void __launch_bounds__(128 * NWN, MINB) k_mm(
    const __nv_bfloat16* __restrict__ Ah, const __nv_bfloat16* __restrict__ Al,
    int M,
    const __nv_bfloat16* __restrict__ Bh, const __nv_bfloat16* __restrict__ Bl,
    const float* __restrict__ bias, int NB,
    float* __restrict__ Of, float* __restrict__ Og,
    __nv_bfloat16* __restrict__ Oh, __nv_bfloat16* __restrict__ Ol, int ldo)
{
    constexpr int NT  = NWN * 32;
    constexpr int NC  = KPAD / 32;
    constexpr int ATB = 128 * 80;
    constexpr int BTB = NT * 80;
    __shared__ __align__(16) char smem[2 * ATB + 2 * BTB];
    char* sAH = smem;
    char* sAL = smem + ATB;
    char* sBH = smem + 2 * ATB;
    char* sBL = smem + 2 * ATB + BTB;

    int t = threadIdx.x, lane = t & 31, wid = t >> 5;
    int wm = wid & 3, wn = wid >> 2;
    int m0 = blockIdx.y * 128, n0 = blockIdx.x * NT;

    int cw = n0 + wn * 32;
    bool act0 = (cw + 0)  < NB;
    bool act1 = (cw + 8)  < NB;
    bool act2 = (cw + 16) < NB;
    bool act3 = (cw + 24) < NB;
    bool act23 = act2 | act3;

    uint32_t sbase = smem_u32(smem);
    int tile = lane >> 3, trow = lane & 7;
    uint32_t aOff = (uint32_t)(((wm * 32 + (tile & 1) * 8 + trow) * 40 + (tile >> 1) * 8) * 2);
    uint32_t bOff = (uint32_t)(((wn * 32 + (tile >> 1) * 8 + trow) * 40 + (tile & 1) * 8) * 2);
    uint32_t aH_addr = sbase + aOff;
    uint32_t aL_addr = sbase + ATB + aOff;
    uint32_t bH_addr = sbase + 2 * ATB + bOff;
    uint32_t bL_addr = sbase + 2 * ATB + BTB + bOff;

    float d[2][4][4];
#pragma unroll
    for (int i = 0; i < 2; i++)
#pragma unroll
        for (int j = 0; j < 4; j++)
#pragma unroll
            for (int q = 0; q < 4; q++) d[i][j][q] = 0.f;

    uint4 rah[NWN == 2 ? 2 : 4], ral[NWN == 2 ? 2 : 4];
    uint4 rbh, rbl, rbh2, rbl2;
    int arow, ahalf, brow, bq;
    if (NWN == 2) { arow = t >> 1; ahalf = t & 1; brow = t >> 1; bq = t & 1; }
    else          { arow = t;      ahalf = 0;     brow = t >> 2; bq = t & 3; }
    int mload = m0 + arow; if (mload >= M) mload = M - 1;

    auto ldregs = [&](int cc) {
        int k0 = cc * 32;
        if (NWN == 2) {
            const char* ah = (const char*)(Ah + (size_t)mload * KPAD + k0) + ahalf * 32;
            const char* al = (const char*)(Al + (size_t)mload * KPAD + k0) + ahalf * 32;
            rah[0] = *(const uint4*)ah;  rah[1] = *(const uint4*)(ah + 16);
            ral[0] = *(const uint4*)al;  ral[1] = *(const uint4*)(al + 16);
            if (t < 128) {
                int n = n0 + brow;
                const char* bh = (const char*)(Bh + (size_t)n * KPAD + k0) + bq * 32;
                const char* bl = (const char*)(Bl + (size_t)n * KPAD + k0) + bq * 32;
                rbh  = *(const uint4*)bh;  rbh2 = *(const uint4*)(bh + 16);
                rbl  = *(const uint4*)bl;  rbl2 = *(const uint4*)(bl + 16);
            }
        } else {
            const char* ah = (const char*)(Ah + (size_t)mload * KPAD + k0);
            const char* al = (const char*)(Al + (size_t)mload * KPAD + k0);
#pragma unroll
            for (int q2 = 0; q2 < 4; q2++) {
                rah[q2] = *(const uint4*)(ah + q2 * 16);
                ral[q2] = *(const uint4*)(al + q2 * 16);
            }
            int n = n0 + brow;
            const char* bh = (const char*)(Bh + (size_t)n * KPAD + k0) + bq * 16;
            const char* bl = (const char*)(Bl + (size_t)n * KPAD + k0) + bq * 16;
            rbh = *(const uint4*)bh;
            rbl = *(const uint4*)bl;
        }
    };

    ldregs(0);
#pragma unroll 1
    for (int cc = 0; cc < NC; cc++) {
        __syncthreads();
        if (NWN == 2) {
            char* pah = sAH + arow * 80 + ahalf * 32;
            char* pal = sAL + arow * 80 + ahalf * 32;
            *(uint4*)pah = rah[0]; *(uint4*)(pah + 16) = rah[1];
            *(uint4*)pal = ral[0]; *(uint4*)(pal + 16) = ral[1];
            if (t < 128) {
                char* pbh = sBH + brow * 80 + bq * 32;
                char* pbl = sBL + brow * 80 + bq * 32;
                *(uint4*)pbh = rbh; *(uint4*)(pbh + 16) = rbh2;
                *(uint4*)pbl = rbl; *(uint4*)(pbl + 16) = rbl2;
            }
        } else {
            char* pah = sAH + arow * 80;
            char* pal = sAL + arow * 80;
#pragma unroll
            for (int q2 = 0; q2 < 4; q2++) {
                *(uint4*)(pah + q2 * 16) = rah[q2];
                *(uint4*)(pal + q2 * 16) = ral[q2];
            }
            char* pbh = sBH + brow * 80 + bq * 16;
            char* pbl = sBL + brow * 80 + bq * 16;
            *(uint4*)pbh = rbh;
            *(uint4*)pbl = rbl;
        }
        __syncthreads();
        if (cc + 1 < NC) ldregs(cc + 1);
#pragma unroll
        for (int kk = 0; kk < 2; kk++) {
            uint32_t aH[2][4], aL[2][4], bH[2][4], bL[2][4];
            ldsm_x4(aH_addr + kk * 32, aH[0]);
            ldsm_x4(aH_addr + 1280 + kk * 32, aH[1]);
            ldsm_x4(aL_addr + kk * 32, aL[0]);
            ldsm_x4(aL_addr + 1280 + kk * 32, aL[1]);
            ldsm_x4(bH_addr + kk * 32, bH[0]);
            ldsm_x4(bL_addr + kk * 32, bL[0]);
            if (act23) {
                ldsm_x4(bH_addr + 1280 + kk * 32, bH[1]);
                ldsm_x4(bL_addr + 1280 + kk * 32, bL[1]);
            }
#pragma unroll
            for (int mf = 0; mf < 2; mf++) {
#pragma unroll
                for (int nf = 0; nf < 4; nf++) {
                    bool act = (nf == 0) ? act0 : (nf == 1) ? act1 : (nf == 2) ? act2 : act3;
                    if (act) {
                        uint32_t* bhp = &bH[nf >> 1][(nf & 1) * 2];
                        uint32_t* blp = &bL[nf >> 1][(nf & 1) * 2];
                        mma_bf16(d[mf][nf], aH[mf], bhp);
                        mma_bf16(d[mf][nf], aH[mf], blp);
                        mma_bf16(d[mf][nf], aL[mf], bhp);
                    }
                }
            }
        }
    }

    // ---------------- epilogue ----------------
    int rbase = lane >> 2, cpair = (lane & 3) * 2;
    float bv[4][2];
#pragma unroll
    for (int nf = 0; nf < 4; nf++) {
        int c = n0 + wn * 32 + nf * 8 + cpair;
        bv[nf][0] = (bias != nullptr && c < NB) ? bias[c] : 0.f;
        bv[nf][1] = (bias != nullptr && c + 1 < NB) ? bias[c + 1] : 0.f;
    }
#pragma unroll
    for (int mf = 0; mf < 2; mf++) {
#pragma unroll
        for (int h = 0; h < 2; h++) {
            int m = m0 + wm * 32 + mf * 16 + h * 8 + rbase;
            if (m >= M) continue;
#pragma unroll
            for (int nf = 0; nf < 4; nf++) {
                int c = n0 + wn * 32 + nf * 8 + cpair;
                float v0 = d[mf][nf][h * 2 + 0] + bv[nf][0];
                float v1 = d[mf][nf][h * 2 + 1] + bv[nf][1];
                if (HAS_ELU) { v0 = elu_f(v0); v1 = elu_f(v1); }
                if (OUTM == 1) {
                    __nv_bfloat16 h0 = __float2bfloat16(v0);
                    __nv_bfloat16 h1v = __float2bfloat16(v1);
                    __nv_bfloat16 l0 = __float2bfloat16(v0 - __bfloat162float(h0));
                    __nv_bfloat16 l1 = __float2bfloat16(v1 - __bfloat162float(h1v));
                    *(ushort2*)&Oh[(size_t)m * ldo + c] =
                        make_ushort2(__bfloat16_as_ushort(h0), __bfloat16_as_ushort(h1v));
                    *(ushort2*)&Ol[(size_t)m * ldo + c] =
                        make_ushort2(__bfloat16_as_ushort(l0), __bfloat16_as_ushort(l1));
                } else if (OUTM == 0) {
                    if (c < ldo)
                        *(float2*)&Of[(size_t)m * ldo + c] = make_float2(v0, v1);
                } else {  // DUAL: c<100 -> Of, 100<=c<NB -> Og (100 even, pairs stay in-region)
                    if (c < 100)
                        *(float2*)&Of[(size_t)m * 100 + c] = make_float2(v0, v1);
                    else if (c < NB)
                        *(float2*)&Og[(size_t)m * 100 + (c - 100)] = make_float2(v0, v1);
                }
            }
        }
    }
}

// ---------------- launch ----------------
extern "C" void kernel_launch(void* const* d_in, const int* in_sizes, int n_in,
                              void* d_out, int out_size) {
    const float* x   = (const float*)d_in[0];
    const int*   src = (const int*)d_in[1];
    const int*   dst = (const int*)d_in[2];
    const float* W1  = (const float*)d_in[3];
    const float* b1  = (const float*)d_in[4];
    const float* Wn  = (const float*)d_in[5];
    const float* Ws  = (const float*)d_in[6];
    const float* b2  = (const float*)d_in[7];
    const float* W3  = (const float*)d_in[8];
    const float* b3  = (const float*)d_in[9];
    float* out = (float*)d_out;

    auto sym = [](const void* s) { void* p = nullptr; cudaGetSymbolAddress(&p, s); return p; };
    __nv_bfloat16* aggh = (__nv_bfloat16*)sym(g_aggh);
    __nv_bfloat16* aggl = (__nv_bfloat16*)sym(g_aggl);
    __nv_bfloat16* h1h  = (__nv_bfloat16*)sym(g_h1h);
    __nv_bfloat16* h1l  = (__nv_bfloat16*)sym(g_h1l);
    __nv_bfloat16* h2h  = (__nv_bfloat16*)sym(g_h2h);
    __nv_bfloat16* h2l  = (__nv_bfloat16*)sym(g_h2l);
    float* hWn   = (float*)sym(g_hWn);
    float* h2pre = (float*)sym(g_h2pre);
    float* biasm = (float*)sym(g_bias_m);
    __nv_bfloat16* B1h  = (__nv_bfloat16*)sym(g_B1h),  *B1l  = (__nv_bfloat16*)sym(g_B1l);
    __nv_bfloat16* BWmh = (__nv_bfloat16*)sym(g_BWmh), *BWml = (__nv_bfloat16*)sym(g_BWml);
    __nv_bfloat16* B3h  = (__nv_bfloat16*)sym(g_B3h),  *B3l  = (__nv_bfloat16*)sym(g_B3l);

    k_zero<<<(NN + 255) / 256, 256>>>();
    k_degrees<<<(EE + 255) / 256, 256>>>(src, dst);
    k_scan_norms<<<SCAN_B, 1024>>>();
    k_fill<<<(EE + 255) / 256, 256>>>(src, dst);
    k_wprep_all<<<(160*128 + 256*160 + 64*128 + 256 + 255) / 256, 256>>>(W1, Wn, Ws, W3, b2);

    int agg_blocks = (NN * 32 + 255) / 256;
    k_agg1<<<agg_blocks, 256>>>(x);

    int MT = (NN + 127) / 128;  // 391

    // h1 = elu(agg @ W1 + b1) -> bf16 hi/lo [NN, 160]
    k_mm<1, 128, 1, true, 4><<<dim3(5, MT), 128>>>(
        aggh, aggl, NN, B1h, B1l, b1, D1,
        nullptr, nullptr, h1h, h1l, KP1);

    // [hWn | h2pre] = h1 @ [Wn | Ws] + [0 | b2] -> dual fp32 [NN, 100] each
    k_mm<2, 160, 2, false, 2><<<dim3(4, MT), 256>>>(
        h1h, h1l, NN, BWmh, BWml, biasm, 200,
        hWn, h2pre, nullptr, nullptr, 100);

    // h2 = elu(h2pre + mean-agg(hWn)) -> bf16 hi/lo [NN, 128]
    k_agg2p<<<agg_blocks, 256>>>();

    // out = elu(h2 @ W3 + b3) -> fp32 [NN, 64]
    k_mm<2, 128, 0, true, 2><<<dim3(1, MT), 256>>>(
        h2h, h2l, NN, B3h, B3l, b3, DOUT,
        out, nullptr, nullptr, nullptr, DOUT);
}

// round 10
// speedup vs baseline: 1.3969x; 1.3969x over previous
#include <cuda_runtime.h>
#include <cuda_bf16.h>
#include <math.h>
#include <stdint.h>

#define NN   50000
#define EE   800000
#define DIN  128
#define D1   150
#define KP1  160     // h1 K-padded (row stride)
#define D2   100
#define LD2  100     // fp32 hWn/neighWn stride
#define KP2  128     // h2 K-padded
#define DOUT 64
#define SCAN_B ((NN + 1023) / 1024)

// ---------------- scratch ----------------
__device__ float g_deg_out[NN];
__device__ int   g_deg_in[NN];
__device__ int   g_off[NN + 1];
__device__ int   g_cur[NN];
__device__ int   g_pref[SCAN_B];
__device__ int   g_csr[EE];
__device__ float g_norm_out[NN];
__device__ float g_norm_in[NN];
__device__ float g_invdeg[NN];

__device__ __align__(16) __nv_bfloat16 g_aggh[(size_t)NN * DIN];
__device__ __align__(16) __nv_bfloat16 g_aggl[(size_t)NN * DIN];
__device__ __align__(16) __nv_bfloat16 g_h1h[(size_t)NN * KP1];
__device__ __align__(16) __nv_bfloat16 g_h1l[(size_t)NN * KP1];
__device__ __align__(16) __nv_bfloat16 g_h2h[(size_t)NN * KP2];
__device__ __align__(16) __nv_bfloat16 g_h2l[(size_t)NN * KP2];
__device__ __align__(16) float g_hWn[(size_t)NN * LD2];
__device__ __align__(16) float g_neighWn[(size_t)NN * LD2];

// weights transposed [NPAD, KPAD] bf16 hi/lo  (B1 padded to 192 rows for 3x64 tiling)
__device__ __align__(16) __nv_bfloat16 g_B1h[192 * 128], g_B1l[192 * 128];
__device__ __align__(16) __nv_bfloat16 g_BWnh[128 * 160], g_BWnl[128 * 160];
__device__ __align__(16) __nv_bfloat16 g_BWsh[128 * 160], g_BWsl[128 * 160];
__device__ __align__(16) __nv_bfloat16 g_B3h[64 * 128],  g_B3l[64 * 128];

__device__ __forceinline__ float elu_f(float v) { return v > 0.f ? v : expm1f(v); }

__device__ __forceinline__ uint32_t smem_u32(const void* p) {
    uint32_t a;
    asm("{ .reg .u64 t; cvta.to.shared.u64 t, %1; cvt.u32.u64 %0, t; }" : "=r"(a) : "l"(p));
    return a;
}
__device__ __forceinline__ void ldsm_x4(uint32_t addr, uint32_t* r) {
    asm volatile("ldmatrix.sync.aligned.m8n8.x4.shared.b16 {%0,%1,%2,%3}, [%4];"
                 : "=r"(r[0]), "=r"(r[1]), "=r"(r[2]), "=r"(r[3]) : "r"(addr));
}
__device__ __forceinline__ void mma_bf16(float* d, const uint32_t* a, const uint32_t* b) {
    asm volatile("mma.sync.aligned.m16n8k16.row.col.f32.bf16.bf16.f32 "
                 "{%0,%1,%2,%3}, {%4,%5,%6,%7}, {%8,%9}, {%0,%1,%2,%3};"
                 : "+f"(d[0]), "+f"(d[1]), "+f"(d[2]), "+f"(d[3])
                 : "r"(a[0]), "r"(a[1]), "r"(a[2]), "r"(a[3]), "r"(b[0]), "r"(b[1]));
}

// ---------------- preprocessing ----------------
__global__ void k_zero() {
    int i = blockIdx.x * blockDim.x + threadIdx.x;
    if (i < NN) { g_deg_out[i] = 0.f; g_deg_in[i] = 0; g_cur[i] = 0; }
    if (i < SCAN_B) g_pref[i] = 0;
}
// 4 edges/thread via int4 (kept from R7: degrees int4 measured beneficial)
__global__ void k_degrees(const int4* __restrict__ src4, const int4* __restrict__ dst4) {
    int i = blockIdx.x * blockDim.x + threadIdx.x;
    if (i >= EE / 4) return;
    int4 s = src4[i], d = dst4[i];
    atomicAdd(&g_deg_out[s.x], 1.f);
    atomicAdd(&g_deg_out[s.y], 1.f);
    atomicAdd(&g_deg_out[s.z], 1.f);
    atomicAdd(&g_deg_out[s.w], 1.f);
    atomicAdd(&g_deg_in[d.x], 1);
    atomicAdd(&g_deg_in[d.y], 1);
    atomicAdd(&g_deg_in[d.z], 1);
    atomicAdd(&g_deg_in[d.w], 1);
}
__global__ void k_scan_norms() {
    __shared__ int s[1024];
    __shared__ int s_carry;
    int tid = threadIdx.x, b = blockIdx.x;
    int i = b * 1024 + tid;
    if (i < NN) {
        g_norm_out[i] = rsqrtf(fmaxf(g_deg_out[i], 1.f));
        float dmx = fmaxf((float)g_deg_in[i], 1.f);
        g_norm_in[i] = rsqrtf(dmx);
        g_invdeg[i]  = 1.f / dmx;
    }
    int v = (i < NN) ? g_deg_in[i] : 0;
    s[tid] = v;
    __syncthreads();
    for (int off = 1; off < 1024; off <<= 1) {
        int t = (tid >= off) ? s[tid - off] : 0;
        __syncthreads();
        s[tid] += t;
        __syncthreads();
    }
    if (tid == 1023) {
        int prev = 0;
        if (b > 0) {
            int pv;
            do { pv = atomicAdd(&g_pref[b - 1], 0); } while (pv == 0);
            prev = pv - 1;
        }
        atomicExch(&g_pref[b], prev + s[1023] + 1);
        s_carry = prev;
    }
    __syncthreads();
    int carry = s_carry;
    if (i < NN) g_off[i + 1] = s[tid] + carry;
    if (i == 0) g_off[0] = 0;
}
// scalar fill: max TLP hides atomic->store chain latency (R6 evidence)
__global__ void k_fill(const int* __restrict__ src, const int* __restrict__ dst) {
    int e = blockIdx.x * blockDim.x + threadIdx.x;
    if (e >= EE) return;
    int d = dst[e];
    int p = atomicAdd(&g_cur[d], 1);
    g_csr[g_off[d] + p] = src[e];
}

// ---------------- fused weight prep ----------------
__device__ __forceinline__ void wsplit(const float* W, int KB, int NB, int KPAD,
                                       __nv_bfloat16* bh, __nv_bfloat16* bl, int idx) {
    int n = idx / KPAD, k = idx % KPAD;
    float v = (n < NB && k < KB) ? W[(size_t)k * NB + n] : 0.f;
    __nv_bfloat16 hv = __float2bfloat16(v);
    bh[idx] = hv;
    bl[idx] = __float2bfloat16(v - __bfloat162float(hv));
}
__global__ void k_wprep_all(const float* __restrict__ W1, const float* __restrict__ Wn,
                            const float* __restrict__ Ws, const float* __restrict__ W3) {
    int i = blockIdx.x * 256 + threadIdx.x;
    const int S1 = 192 * 128, S2 = 128 * 160, S3 = 128 * 160, S4 = 64 * 128;
    if (i < S1) { wsplit(W1, DIN, D1, 128, g_B1h, g_B1l, i); return; }
    i -= S1;
    if (i < S2) { wsplit(Wn, D1, D2, 160, g_BWnh, g_BWnl, i); return; }
    i -= S2;
    if (i < S3) { wsplit(Ws, D1, D2, 160, g_BWsh, g_BWsl, i); return; }
    i -= S3;
    if (i < S4) { wsplit(W3, D2, DOUT, 128, g_B3h, g_B3l, i); return; }
}

// ---------------- layer-1 aggregation -> bf16 hi/lo ----------------
__global__ void k_agg1(const float* __restrict__ x) {
    int w    = (blockIdx.x * blockDim.x + threadIdx.x) >> 5;
    int lane = threadIdx.x & 31;
    if (w >= NN) return;
    int beg = g_off[w], end = g_off[w + 1];
    const float4* X = (const float4*)x;
    float4 acc = make_float4(0.f, 0.f, 0.f, 0.f);
    int j = beg;
    for (; j + 3 < end; j += 4) {
        int s0 = g_csr[j], s1 = g_csr[j + 1], s2 = g_csr[j + 2], s3 = g_csr[j + 3];
        float w0 = g_norm_out[s0], w1 = g_norm_out[s1];
        float w2 = g_norm_out[s2], w3 = g_norm_out[s3];
        float4 v0 = X[(size_t)s0 * 32 + lane];
        float4 v1 = X[(size_t)s1 * 32 + lane];
        float4 v2 = X[(size_t)s2 * 32 + lane];
        float4 v3 = X[(size_t)s3 * 32 + lane];
        acc.x += v0.x * w0 + v1.x * w1 + v2.x * w2 + v3.x * w3;
        acc.y += v0.y * w0 + v1.y * w1 + v2.y * w2 + v3.y * w3;
        acc.z += v0.z * w0 + v1.z * w1 + v2.z * w2 + v3.z * w3;
        acc.w += v0.w * w0 + v1.w * w1 + v2.w * w2 + v3.w * w3;
    }
    for (; j < end; j++) {
        int s0 = g_csr[j];
        float w0 = g_norm_out[s0];
        float4 v0 = X[(size_t)s0 * 32 + lane];
        acc.x += v0.x * w0; acc.y += v0.y * w0; acc.z += v0.z * w0; acc.w += v0.w * w0;
    }
    float ni = g_norm_in[w];
    float v[4] = { acc.x * ni, acc.y * ni, acc.z * ni, acc.w * ni };
    __nv_bfloat16 hv[4], lv[4];
#pragma unroll
    for (int q = 0; q < 4; q++) {
        hv[q] = __float2bfloat16(v[q]);
        lv[q] = __float2bfloat16(v[q] - __bfloat162float(hv[q]));
    }
    *(ushort4*)&g_aggh[(size_t)w * DIN + lane * 4] =
        make_ushort4(__bfloat16_as_ushort(hv[0]), __bfloat16_as_ushort(hv[1]),
                     __bfloat16_as_ushort(hv[2]), __bfloat16_as_ushort(hv[3]));
    *(ushort4*)&g_aggl[(size_t)w * DIN + lane * 4] =
        make_ushort4(__bfloat16_as_ushort(lv[0]), __bfloat16_as_ushort(lv[1]),
                     __bfloat16_as_ushort(lv[2]), __bfloat16_as_ushort(lv[3]));
}

// ---------------- layer-2 aggregation of hWn (fp32, 100 cols = 25 float4) --------
__global__ void k_agg2() {
    int w    = (blockIdx.x * blockDim.x + threadIdx.x) >> 5;
    int lane = threadIdx.x & 31;
    if (w >= NN) return;
    if (lane >= LD2 / 4) return;
    int beg = g_off[w], end = g_off[w + 1];
    const float4* X = (const float4*)g_hWn;
    float4 acc = make_float4(0.f, 0.f, 0.f, 0.f);
    int j = beg;
    for (; j + 1 < end; j += 2) {
        int s0 = g_csr[j], s1 = g_csr[j + 1];
        float4 v0 = X[(size_t)s0 * (LD2 / 4) + lane];
        float4 v1 = X[(size_t)s1 * (LD2 / 4) + lane];
        acc.x += v0.x + v1.x; acc.y += v0.y + v1.y;
        acc.z += v0.z + v1.z; acc.w += v0.w + v1.w;
    }
    if (j < end) {
        int s0 = g_csr[j];
        float4 v0 = X[(size_t)s0 * (LD2 / 4) + lane];
        acc.x += v0.x; acc.y += v0.y; acc.z += v0.z; acc.w += v0.w;
    }
    float inv = g_invdeg[w];
    acc.x *= inv; acc.y *= inv; acc.z *= inv; acc.w *= inv;
    ((float4*)g_neighWn)[(size_t)w * (LD2 / 4) + lane] = acc;
}

// ---------------- fused 3-term bf16-split GEMM with frag skipping ----------------
// D = Ahi.Bhi + Ahi.Blo + Alo.Bhi ; block 128M x 64N, 8 warps (4M x 2N)
// n8 fragments whose column base >= NB are skipped (warp-uniform predicate).
template<int KPAD, bool HAS_EPI, bool HAS_C0, bool OUT_SPLIT>
__global__ void __launch_bounds__(256, 2) k_mm(
    const __nv_bfloat16* __restrict__ Ah, const __nv_bfloat16* __restrict__ Al,
    int M,
    const __nv_bfloat16* __restrict__ Bh, const __nv_bfloat16* __restrict__ Bl,
    const float* __restrict__ bias, int NB,
    const float* __restrict__ C0, int ldc0,
    float* __restrict__ Of, __nv_bfloat16* __restrict__ Oh,
    __nv_bfloat16* __restrict__ Ol, int ldo)
{
    constexpr int NT  = 64;
    constexpr int NC  = KPAD / 32;
    constexpr int ATB = 128 * 80;            // A tile bytes (rows padded to 40 bf16)
    constexpr int BTB = NT * 80;
    __shared__ __align__(16) char smem[2 * ATB + 2 * BTB];
    char* sAH = smem;
    char* sAL = smem + ATB;
    char* sBH = smem + 2 * ATB;
    char* sBL = smem + 2 * ATB + BTB;

    int t = threadIdx.x, lane = t & 31, wid = t >> 5;
    int wm = wid & 3, wn = wid >> 2;
    int m0 = blockIdx.y * 128, n0 = blockIdx.x * NT;

    // warp-uniform fragment activity
    int cw = n0 + wn * 32;
    bool act0 = (cw + 0)  < NB;
    bool act1 = (cw + 8)  < NB;
    bool act2 = (cw + 16) < NB;
    bool act3 = (cw + 24) < NB;
    bool act23 = act2 | act3;

    uint32_t sbase = smem_u32(smem);
    int tile = lane >> 3, trow = lane & 7;
    uint32_t aOff = (uint32_t)(((wm * 32 + (tile & 1) * 8 + trow) * 40 + (tile >> 1) * 8) * 2);
    uint32_t bOff = (uint32_t)(((wn * 32 + (tile >> 1) * 8 + trow) * 40 + (tile & 1) * 8) * 2);
    uint32_t aH_addr = sbase + aOff;
    uint32_t aL_addr = sbase + ATB + aOff;
    uint32_t bH_addr = sbase + 2 * ATB + bOff;
    uint32_t bL_addr = sbase + 2 * ATB + BTB + bOff;

    float d[2][4][4];
#pragma unroll
    for (int i = 0; i < 2; i++)
#pragma unroll
        for (int j = 0; j < 4; j++)
#pragma unroll
            for (int q = 0; q < 4; q++) d[i][j][q] = 0.f;

    uint4 rah[2], ral[2];
    uint4 rbh, rbl, rbh2, rbl2;
    int arow = t >> 1, ahalf = t & 1, brow = t >> 1, bq = t & 1;
    int mload = m0 + arow; if (mload >= M) mload = M - 1;

    auto ldregs = [&](int cc) {
        int k0 = cc * 32;
        const char* ah = (const char*)(Ah + (size_t)mload * KPAD + k0) + ahalf * 32;
        const char* al = (const char*)(Al + (size_t)mload * KPAD + k0) + ahalf * 32;
        rah[0] = *(const uint4*)ah;  rah[1] = *(const uint4*)(ah + 16);
        ral[0] = *(const uint4*)al;  ral[1] = *(const uint4*)(al + 16);
        if (t < NT * 2) {
            int n = n0 + brow;
            const char* bh = (const char*)(Bh + (size_t)n * KPAD + k0) + bq * 32;
            const char* bl = (const char*)(Bl + (size_t)n * KPAD + k0) + bq * 32;
            rbh  = *(const uint4*)bh;  rbh2 = *(const uint4*)(bh + 16);
            rbl  = *(const uint4*)bl;  rbl2 = *(const uint4*)(bl + 16);
        }
    };

    ldregs(0);
#pragma unroll 1
    for (int cc = 0; cc < NC; cc++) {
        __syncthreads();
        {
            char* pah = sAH + arow * 80 + ahalf * 32;
            char* pal = sAL + arow * 80 + ahalf * 32;
            *(uint4*)pah = rah[0]; *(uint4*)(pah + 16) = rah[1];
            *(uint4*)pal = ral[0]; *(uint4*)(pal + 16) = ral[1];
            if (t < NT * 2) {
                char* pbh = sBH + brow * 80 + bq * 32;
                char* pbl = sBL + brow * 80 + bq * 32;
                *(uint4*)pbh = rbh; *(uint4*)(pbh + 16) = rbh2;
                *(uint4*)pbl = rbl; *(uint4*)(pbl + 16) = rbl2;
            }
        }
        __syncthreads();
        if (cc + 1 < NC) ldregs(cc + 1);
#pragma unroll
        for (int kk = 0; kk < 2; kk++) {
            uint32_t aH[2][4], aL[2][4], bH[2][4], bL[2][4];
            ldsm_x4(aH_addr + kk * 32, aH[0]);
            ldsm_x4(aH_addr + 1280 + kk * 32, aH[1]);
            ldsm_x4(aL_addr + kk * 32, aL[0]);
            ldsm_x4(aL_addr + 1280 + kk * 32, aL[1]);
            ldsm_x4(bH_addr + kk * 32, bH[0]);
            ldsm_x4(bL_addr + kk * 32, bL[0]);
            if (act23) {
                ldsm_x4(bH_addr + 1280 + kk * 32, bH[1]);
                ldsm_x4(bL_addr + 1280 + kk * 32, bL[1]);
            }
#pragma unroll
            for (int mf = 0; mf < 2; mf++) {
#pragma unroll
                for (int nf = 0; nf < 4; nf++) {
                    bool act = (nf == 0) ? act0 : (nf == 1) ? act1 : (nf == 2) ? act2 : act3;
                    if (act) {
                        uint32_t* bhp = &bH[nf >> 1][(nf & 1) * 2];
                        uint32_t* blp = &bL[nf >> 1][(nf & 1) * 2];
                        mma_bf16(d[mf][nf], aH[mf], bhp);
                        mma_bf16(d[mf][nf], aH[mf], blp);
                        mma_bf16(d[mf][nf], aL[mf], bhp);
                    }
                }
            }
        }
    }

    // ---------------- epilogue ----------------
    int rbase = lane >> 2, cpair = (lane & 3) * 2;
    float bv[4][2];
#pragma unroll
    for (int nf = 0; nf < 4; nf++) {
        int c = n0 + wn * 32 + nf * 8 + cpair;
        bv[nf][0] = (HAS_EPI && c < NB) ? bias[c] : 0.f;
        bv[nf][1] = (HAS_EPI && c + 1 < NB) ? bias[c + 1] : 0.f;
    }
#pragma unroll
    for (int mf = 0; mf < 2; mf++) {
#pragma unroll
        for (int h = 0; h < 2; h++) {
            int m = m0 + wm * 32 + mf * 16 + h * 8 + rbase;
            if (m >= M) continue;
#pragma unroll
            for (int nf = 0; nf < 4; nf++) {
                int c = n0 + wn * 32 + nf * 8 + cpair;
                float v0 = d[mf][nf][h * 2 + 0] + bv[nf][0];
                float v1 = d[mf][nf][h * 2 + 1] + bv[nf][1];
                if (HAS_C0) {
                    if (c < ldc0)     v0 += C0[(size_t)m * ldc0 + c];
                    if (c + 1 < ldc0) v1 += C0[(size_t)m * ldc0 + c + 1];
                }
                if (HAS_EPI) { v0 = elu_f(v0); v1 = elu_f(v1); }
                if (OUT_SPLIT) {
                    if (c < ldo) {
                        __nv_bfloat16 h0 = __float2bfloat16(v0);
                        __nv_bfloat16 h1v = __float2bfloat16(v1);
                        __nv_bfloat16 l0 = __float2bfloat16(v0 - __bfloat162float(h0));
                        __nv_bfloat16 l1 = __float2bfloat16(v1 - __bfloat162float(h1v));
                        *(ushort2*)&Oh[(size_t)m * ldo + c] =
                            make_ushort2(__bfloat16_as_ushort(h0), __bfloat16_as_ushort(h1v));
                        *(ushort2*)&Ol[(size_t)m * ldo + c] =
                            make_ushort2(__bfloat16_as_ushort(l0), __bfloat16_as_ushort(l1));
                    }
                } else {
                    if (c < ldo)
                        *(float2*)&Of[(size_t)m * ldo + c] = make_float2(v0, v1);
                }
            }
        }
    }
}

// ---------------- launch ----------------
extern "C" void kernel_launch(void* const* d_in, const int* in_sizes, int n_in,
                              void* d_out, int out_size) {
    const float* x   = (const float*)d_in[0];
    const int*   src = (const int*)d_in[1];
    const int*   dst = (const int*)d_in[2];
    const float* W1  = (const float*)d_in[3];
    const float* b1  = (const float*)d_in[4];
    const float* Wn  = (const float*)d_in[5];
    const float* Ws  = (const float*)d_in[6];
    const float* b2  = (const float*)d_in[7];
    const float* W3  = (const float*)d_in[8];
    const float* b3  = (const float*)d_in[9];
    float* out = (float*)d_out;

    auto sym = [](const void* s) { void* p = nullptr; cudaGetSymbolAddress(&p, s); return p; };
    __nv_bfloat16* aggh = (__nv_bfloat16*)sym(g_aggh);
    __nv_bfloat16* aggl = (__nv_bfloat16*)sym(g_aggl);
    __nv_bfloat16* h1h  = (__nv_bfloat16*)sym(g_h1h);
    __nv_bfloat16* h1l  = (__nv_bfloat16*)sym(g_h1l);
    __nv_bfloat16* h2h  = (__nv_bfloat16*)sym(g_h2h);
    __nv_bfloat16* h2l  = (__nv_bfloat16*)sym(g_h2l);
    float* hWn    = (float*)sym(g_hWn);
    float* neighW = (float*)sym(g_neighWn);
    __nv_bfloat16* B1h  = (__nv_bfloat16*)sym(g_B1h),  *B1l  = (__nv_bfloat16*)sym(g_B1l);
    __nv_bfloat16* BWnh = (__nv_bfloat16*)sym(g_BWnh), *BWnl = (__nv_bfloat16*)sym(g_BWnl);
    __nv_bfloat16* BWsh = (__nv_bfloat16*)sym(g_BWsh), *BWsl = (__nv_bfloat16*)sym(g_BWsl);
    __nv_bfloat16* B3h  = (__nv_bfloat16*)sym(g_B3h),  *B3l  = (__nv_bfloat16*)sym(g_B3l);

    k_zero<<<(NN + 255) / 256, 256>>>();
    k_degrees<<<(EE / 4 + 255) / 256, 256>>>((const int4*)src, (const int4*)dst);
    k_scan_norms<<<SCAN_B, 1024>>>();
    k_fill<<<(EE + 255) / 256, 256>>>(src, dst);
    k_wprep_all<<<(192*128 + 128*160*2 + 64*128 + 255) / 256, 256>>>(W1, Wn, Ws, W3);

    int agg_blocks = (NN * 32 + 255) / 256;
    k_agg1<<<agg_blocks, 256>>>(x);

    int MT = (NN + 127) / 128;  // 391

    // h1 = elu(agg @ W1 + b1) -> bf16 hi/lo [NN, 160]; 3x(128x64) tiles
    k_mm<128, true, false, true><<<dim3(3, MT), 256>>>(
        aggh, aggl, NN, B1h, B1l, b1, D1, nullptr, 0,
        nullptr, h1h, h1l, KP1);

    // hWn = h1 @ Wn -> fp32 [NN, 100]
    k_mm<160, false, false, false><<<dim3(2, MT), 256>>>(
        h1h, h1l, NN, BWnh, BWnl, nullptr, D2, nullptr, 0,
        hWn, nullptr, nullptr, LD2);

    k_agg2<<<agg_blocks, 256>>>();

    // h2 = elu(h1 @ Ws + neighWn + b2) -> bf16 hi/lo [NN, 128]
    k_mm<160, true, true, true><<<dim3(2, MT), 256>>>(
        h1h, h1l, NN, BWsh, BWsl, b2, D2, neighW, LD2,
        nullptr, h2h, h2l, KP2);

    // out = elu(h2 @ W3 + b3) -> fp32 [NN, 64]
    k_mm<128, true, false, false><<<dim3(1, MT), 256>>>(
        h2h, h2l, NN, B3h, B3l, b3, DOUT, nullptr, 0,
        out, nullptr, nullptr, DOUT);
}

// round 11
// speedup vs baseline: 1.4952x; 1.0704x over previous
#include <cuda_runtime.h>
#include <cuda_bf16.h>
#include <math.h>
#include <stdint.h>

#define NN   50000
#define EE   800000
#define DIN  128
#define D1   150
#define KP1  160     // h1 K-padded (row stride)
#define D2   100
#define LD2  100     // fp32 hWn/neighWn stride
#define KP2  128     // h2 K-padded
#define DOUT 64
#define SCAN_B ((NN + 1023) / 1024)

// ---------------- scratch ----------------
__device__ float g_deg_out[NN];
__device__ int   g_deg_in[NN];
__device__ int   g_off[NN + 1];
__device__ int   g_cur[NN];
__device__ int   g_pref[SCAN_B];
__device__ int   g_csr[EE];
__device__ float g_norm_out[NN];
__device__ float g_norm_in[NN];
__device__ float g_invdeg[NN];

__device__ __align__(16) __nv_bfloat16 g_aggh[(size_t)NN * DIN];
__device__ __align__(16) __nv_bfloat16 g_aggl[(size_t)NN * DIN];
__device__ __align__(16) __nv_bfloat16 g_h1h[(size_t)NN * KP1];
__device__ __align__(16) __nv_bfloat16 g_h1l[(size_t)NN * KP1];
__device__ __align__(16) __nv_bfloat16 g_h2h[(size_t)NN * KP2];
__device__ __align__(16) __nv_bfloat16 g_h2l[(size_t)NN * KP2];
__device__ __align__(16) float g_hWn[(size_t)NN * LD2];
__device__ __align__(16) float g_neighWn[(size_t)NN * LD2];

// weights transposed [NPAD, KPAD] bf16 hi/lo  (B1 padded to 192 rows for 3x64 tiling)
__device__ __align__(16) __nv_bfloat16 g_B1h[192 * 128], g_B1l[192 * 128];
__device__ __align__(16) __nv_bfloat16 g_BWnh[128 * 160], g_BWnl[128 * 160];
__device__ __align__(16) __nv_bfloat16 g_BWsh[128 * 160], g_BWsl[128 * 160];
__device__ __align__(16) __nv_bfloat16 g_B3h[64 * 128],  g_B3l[64 * 128];

// fast ELU: expm1f is a ~20-30 instr software routine; __expf is MUFU-based (~5).
// exp(v)-1 cancellation only matters for |v|<<1 where abs err ~1e-7 -> negligible
// in the aggregate relative-error norm.
__device__ __forceinline__ float elu_f(float v) {
    return v > 0.f ? v : (__expf(v) - 1.f);
}

__device__ __forceinline__ uint32_t smem_u32(const void* p) {
    uint32_t a;
    asm("{ .reg .u64 t; cvta.to.shared.u64 t, %1; cvt.u32.u64 %0, t; }" : "=r"(a) : "l"(p));
    return a;
}
__device__ __forceinline__ void ldsm_x4(uint32_t addr, uint32_t* r) {
    asm volatile("ldmatrix.sync.aligned.m8n8.x4.shared.b16 {%0,%1,%2,%3}, [%4];"
                 : "=r"(r[0]), "=r"(r[1]), "=r"(r[2]), "=r"(r[3]) : "r"(addr));
}
__device__ __forceinline__ void mma_bf16(float* d, const uint32_t* a, const uint32_t* b) {
    asm volatile("mma.sync.aligned.m16n8k16.row.col.f32.bf16.bf16.f32 "
                 "{%0,%1,%2,%3}, {%4,%5,%6,%7}, {%8,%9}, {%0,%1,%2,%3};"
                 : "+f"(d[0]), "+f"(d[1]), "+f"(d[2]), "+f"(d[3])
                 : "r"(a[0]), "r"(a[1]), "r"(a[2]), "r"(a[3]), "r"(b[0]), "r"(b[1]));
}

// ---------------- preprocessing ----------------
__global__ void k_zero() {
    int i = blockIdx.x * blockDim.x + threadIdx.x;
    if (i < NN) { g_deg_out[i] = 0.f; g_deg_in[i] = 0; }
    if (i < SCAN_B) g_pref[i] = 0;
}
// 4 edges/thread via int4 (kept from R7: degrees int4 measured beneficial)
__global__ void k_degrees(const int4* __restrict__ src4, const int4* __restrict__ dst4) {
    int i = blockIdx.x * blockDim.x + threadIdx.x;
    if (i >= EE / 4) return;
    int4 s = src4[i], d = dst4[i];
    atomicAdd(&g_deg_out[s.x], 1.f);
    atomicAdd(&g_deg_out[s.y], 1.f);
    atomicAdd(&g_deg_out[s.z], 1.f);
    atomicAdd(&g_deg_out[s.w], 1.f);
    atomicAdd(&g_deg_in[d.x], 1);
    atomicAdd(&g_deg_in[d.y], 1);
    atomicAdd(&g_deg_in[d.z], 1);
    atomicAdd(&g_deg_in[d.w], 1);
}
__global__ void k_scan_norms() {
    __shared__ int s[1024];
    __shared__ int s_carry;
    int tid = threadIdx.x, b = blockIdx.x;
    int i = b * 1024 + tid;
    if (i < NN) {
        g_norm_out[i] = rsqrtf(fmaxf(g_deg_out[i], 1.f));
        float dmx = fmaxf((float)g_deg_in[i], 1.f);
        g_norm_in[i] = rsqrtf(dmx);
        g_invdeg[i]  = 1.f / dmx;
    }
    int v = (i < NN) ? g_deg_in[i] : 0;
    s[tid] = v;
    __syncthreads();
    for (int off = 1; off < 1024; off <<= 1) {
        int t = (tid >= off) ? s[tid - off] : 0;
        __syncthreads();
        s[tid] += t;
        __syncthreads();
    }
    if (tid == 1023) {
        int prev = 0;
        if (b > 0) {
            int pv;
            do { pv = atomicAdd(&g_pref[b - 1], 0); } while (pv == 0);
            prev = pv - 1;
        }
        atomicExch(&g_pref[b], prev + s[1023] + 1);
        s_carry = prev;
    }
    __syncthreads();
    int carry = s_carry;
    if (i < NN) {
        g_off[i + 1] = s[tid] + carry;
        g_cur[i] = s[tid] + carry - v;   // exclusive prefix: fill writes direct
    }
    if (i == 0) g_off[0] = 0;
}
// fill with pre-initialized cursor: load dst -> atomic -> store (no g_off load)
__global__ void k_fill(const int* __restrict__ src, const int* __restrict__ dst) {
    int e = blockIdx.x * blockDim.x + threadIdx.x;
    if (e >= EE) return;
    int d = dst[e];
    int p = atomicAdd(&g_cur[d], 1);
    g_csr[p] = src[e];
}

// ---------------- fused weight prep ----------------
__device__ __forceinline__ void wsplit(const float* W, int KB, int NB, int KPAD,
                                       __nv_bfloat16* bh, __nv_bfloat16* bl, int idx) {
    int n = idx / KPAD, k = idx % KPAD;
    float v = (n < NB && k < KB) ? W[(size_t)k * NB + n] : 0.f;
    __nv_bfloat16 hv = __float2bfloat16(v);
    bh[idx] = hv;
    bl[idx] = __float2bfloat16(v - __bfloat162float(hv));
}
__global__ void k_wprep_all(const float* __restrict__ W1, const float* __restrict__ Wn,
                            const float* __restrict__ Ws, const float* __restrict__ W3) {
    int i = blockIdx.x * 256 + threadIdx.x;
    const int S1 = 192 * 128, S2 = 128 * 160, S3 = 128 * 160, S4 = 64 * 128;
    if (i < S1) { wsplit(W1, DIN, D1, 128, g_B1h, g_B1l, i); return; }
    i -= S1;
    if (i < S2) { wsplit(Wn, D1, D2, 160, g_BWnh, g_BWnl, i); return; }
    i -= S2;
    if (i < S3) { wsplit(Ws, D1, D2, 160, g_BWsh, g_BWsl, i); return; }
    i -= S3;
    if (i < S4) { wsplit(W3, D2, DOUT, 128, g_B3h, g_B3l, i); return; }
}

// ---------------- layer-1 aggregation -> bf16 hi/lo ----------------
__global__ void k_agg1(const float* __restrict__ x) {
    int w    = (blockIdx.x * blockDim.x + threadIdx.x) >> 5;
    int lane = threadIdx.x & 31;
    if (w >= NN) return;
    int beg = g_off[w], end = g_off[w + 1];
    const float4* X = (const float4*)x;
    float4 acc = make_float4(0.f, 0.f, 0.f, 0.f);
    int j = beg;
    for (; j + 3 < end; j += 4) {
        int s0 = g_csr[j], s1 = g_csr[j + 1], s2 = g_csr[j + 2], s3 = g_csr[j + 3];
        float w0 = g_norm_out[s0], w1 = g_norm_out[s1];
        float w2 = g_norm_out[s2], w3 = g_norm_out[s3];
        float4 v0 = X[(size_t)s0 * 32 + lane];
        float4 v1 = X[(size_t)s1 * 32 + lane];
        float4 v2 = X[(size_t)s2 * 32 + lane];
        float4 v3 = X[(size_t)s3 * 32 + lane];
        acc.x += v0.x * w0 + v1.x * w1 + v2.x * w2 + v3.x * w3;
        acc.y += v0.y * w0 + v1.y * w1 + v2.y * w2 + v3.y * w3;
        acc.z += v0.z * w0 + v1.z * w1 + v2.z * w2 + v3.z * w3;
        acc.w += v0.w * w0 + v1.w * w1 + v2.w * w2 + v3.w * w3;
    }
    for (; j < end; j++) {
        int s0 = g_csr[j];
        float w0 = g_norm_out[s0];
        float4 v0 = X[(size_t)s0 * 32 + lane];
        acc.x += v0.x * w0; acc.y += v0.y * w0; acc.z += v0.z * w0; acc.w += v0.w * w0;
    }
    float ni = g_norm_in[w];
    float v[4] = { acc.x * ni, acc.y * ni, acc.z * ni, acc.w * ni };
    __nv_bfloat16 hv[4], lv[4];
#pragma unroll
    for (int q = 0; q < 4; q++) {
        hv[q] = __float2bfloat16(v[q]);
        lv[q] = __float2bfloat16(v[q] - __bfloat162float(hv[q]));
    }
    *(ushort4*)&g_aggh[(size_t)w * DIN + lane * 4] =
        make_ushort4(__bfloat16_as_ushort(hv[0]), __bfloat16_as_ushort(hv[1]),
                     __bfloat16_as_ushort(hv[2]), __bfloat16_as_ushort(hv[3]));
    *(ushort4*)&g_aggl[(size_t)w * DIN + lane * 4] =
        make_ushort4(__bfloat16_as_ushort(lv[0]), __bfloat16_as_ushort(lv[1]),
                     __bfloat16_as_ushort(lv[2]), __bfloat16_as_ushort(lv[3]));
}

// ---------------- layer-2 aggregation of hWn (fp32, 100 cols = 25 float4) --------
__global__ void k_agg2() {
    int w    = (blockIdx.x * blockDim.x + threadIdx.x) >> 5;
    int lane = threadIdx.x & 31;
    if (w >= NN) return;
    if (lane >= LD2 / 4) return;
    int beg = g_off[w], end = g_off[w + 1];
    const float4* X = (const float4*)g_hWn;
    float4 acc = make_float4(0.f, 0.f, 0.f, 0.f);
    int j = beg;
    for (; j + 1 < end; j += 2) {
        int s0 = g_csr[j], s1 = g_csr[j + 1];
        float4 v0 = X[(size_t)s0 * (LD2 / 4) + lane];
        float4 v1 = X[(size_t)s1 * (LD2 / 4) + lane];
        acc.x += v0.x + v1.x; acc.y += v0.y + v1.y;
        acc.z += v0.z + v1.z; acc.w += v0.w + v1.w;
    }
    if (j < end) {
        int s0 = g_csr[j];
        float4 v0 = X[(size_t)s0 * (LD2 / 4) + lane];
        acc.x += v0.x; acc.y += v0.y; acc.z += v0.z; acc.w += v0.w;
    }
    float inv = g_invdeg[w];
    acc.x *= inv; acc.y *= inv; acc.z *= inv; acc.w *= inv;
    ((float4*)g_neighWn)[(size_t)w * (LD2 / 4) + lane] = acc;
}

// ---------------- fused 3-term bf16-split GEMM with frag skipping ----------------
// D = Ahi.Bhi + Ahi.Blo + Alo.Bhi ; block 128M x 64N, 8 warps (4M x 2N)
// n8 fragments whose column base >= NB are skipped (warp-uniform predicate).
template<int KPAD, bool HAS_EPI, bool HAS_C0, bool OUT_SPLIT>
__global__ void __launch_bounds__(256, 2) k_mm(
    const __nv_bfloat16* __restrict__ Ah, const __nv_bfloat16* __restrict__ Al,
    int M,
    const __nv_bfloat16* __restrict__ Bh, const __nv_bfloat16* __restrict__ Bl,
    const float* __restrict__ bias, int NB,
    const float* __restrict__ C0, int ldc0,
    float* __restrict__ Of, __nv_bfloat16* __restrict__ Oh,
    __nv_bfloat16* __restrict__ Ol, int ldo)
{
    constexpr int NT  = 64;
    constexpr int NC  = KPAD / 32;
    constexpr int ATB = 128 * 80;            // A tile bytes (rows padded to 40 bf16)
    constexpr int BTB = NT * 80;
    __shared__ __align__(16) char smem[2 * ATB + 2 * BTB];
    char* sAH = smem;
    char* sAL = smem + ATB;
    char* sBH = smem + 2 * ATB;
    char* sBL = smem + 2 * ATB + BTB;

    int t = threadIdx.x, lane = t & 31, wid = t >> 5;
    int wm = wid & 3, wn = wid >> 2;
    int m0 = blockIdx.y * 128, n0 = blockIdx.x * NT;

    // warp-uniform fragment activity
    int cw = n0 + wn * 32;
    bool act0 = (cw + 0)  < NB;
    bool act1 = (cw + 8)  < NB;
    bool act2 = (cw + 16) < NB;
    bool act3 = (cw + 24) < NB;
    bool act23 = act2 | act3;

    uint32_t sbase = smem_u32(smem);
    int tile = lane >> 3, trow = lane & 7;
    uint32_t aOff = (uint32_t)(((wm * 32 + (tile & 1) * 8 + trow) * 40 + (tile >> 1) * 8) * 2);
    uint32_t bOff = (uint32_t)(((wn * 32 + (tile >> 1) * 8 + trow) * 40 + (tile & 1) * 8) * 2);
    uint32_t aH_addr = sbase + aOff;
    uint32_t aL_addr = sbase + ATB + aOff;
    uint32_t bH_addr = sbase + 2 * ATB + bOff;
    uint32_t bL_addr = sbase + 2 * ATB + BTB + bOff;

    float d[2][4][4];
#pragma unroll
    for (int i = 0; i < 2; i++)
#pragma unroll
        for (int j = 0; j < 4; j++)
#pragma unroll
            for (int q = 0; q < 4; q++) d[i][j][q] = 0.f;

    uint4 rah[2], ral[2];
    uint4 rbh, rbl, rbh2, rbl2;
    int arow = t >> 1, ahalf = t & 1, brow = t >> 1, bq = t & 1;
    int mload = m0 + arow; if (mload >= M) mload = M - 1;

    auto ldregs = [&](int cc) {
        int k0 = cc * 32;
        const char* ah = (const char*)(Ah + (size_t)mload * KPAD + k0) + ahalf * 32;
        const char* al = (const char*)(Al + (size_t)mload * KPAD + k0) + ahalf * 32;
        rah[0] = *(const uint4*)ah;  rah[1] = *(const uint4*)(ah + 16);
        ral[0] = *(const uint4*)al;  ral[1] = *(const uint4*)(al + 16);
        if (t < NT * 2) {
            int n = n0 + brow;
            const char* bh = (const char*)(Bh + (size_t)n * KPAD + k0) + bq * 32;
            const char* bl = (const char*)(Bl + (size_t)n * KPAD + k0) + bq * 32;
            rbh  = *(const uint4*)bh;  rbh2 = *(const uint4*)(bh + 16);
            rbl  = *(const uint4*)bl;  rbl2 = *(const uint4*)(bl + 16);
        }
    };

    ldregs(0);
#pragma unroll 1
    for (int cc = 0; cc < NC; cc++) {
        __syncthreads();
        {
            char* pah = sAH + arow * 80 + ahalf * 32;
            char* pal = sAL + arow * 80 + ahalf * 32;
            *(uint4*)pah = rah[0]; *(uint4*)(pah + 16) = rah[1];
            *(uint4*)pal = ral[0]; *(uint4*)(pal + 16) = ral[1];
            if (t < NT * 2) {
                char* pbh = sBH + brow * 80 + bq * 32;
                char* pbl = sBL + brow * 80 + bq * 32;
                *(uint4*)pbh = rbh; *(uint4*)(pbh + 16) = rbh2;
                *(uint4*)pbl = rbl; *(uint4*)(pbl + 16) = rbl2;
            }
        }
        __syncthreads();
        if (cc + 1 < NC) ldregs(cc + 1);
#pragma unroll
        for (int kk = 0; kk < 2; kk++) {
            uint32_t aH[2][4], aL[2][4], bH[2][4], bL[2][4];
            ldsm_x4(aH_addr + kk * 32, aH[0]);
            ldsm_x4(aH_addr + 1280 + kk * 32, aH[1]);
            ldsm_x4(aL_addr + kk * 32, aL[0]);
            ldsm_x4(aL_addr + 1280 + kk * 32, aL[1]);
            ldsm_x4(bH_addr + kk * 32, bH[0]);
            ldsm_x4(bL_addr + kk * 32, bL[0]);
            if (act23) {
                ldsm_x4(bH_addr + 1280 + kk * 32, bH[1]);
                ldsm_x4(bL_addr + 1280 + kk * 32, bL[1]);
            }
#pragma unroll
            for (int mf = 0; mf < 2; mf++) {
#pragma unroll
                for (int nf = 0; nf < 4; nf++) {
                    bool act = (nf == 0) ? act0 : (nf == 1) ? act1 : (nf == 2) ? act2 : act3;
                    if (act) {
                        uint32_t* bhp = &bH[nf >> 1][(nf & 1) * 2];
                        uint32_t* blp = &bL[nf >> 1][(nf & 1) * 2];
                        mma_bf16(d[mf][nf], aH[mf], bhp);
                        mma_bf16(d[mf][nf], aH[mf], blp);
                        mma_bf16(d[mf][nf], aL[mf], bhp);
                    }
                }
            }
        }
    }

    // ---------------- epilogue ----------------
    int rbase = lane >> 2, cpair = (lane & 3) * 2;
    float bv[4][2];
#pragma unroll
    for (int nf = 0; nf < 4; nf++) {
        int c = n0 + wn * 32 + nf * 8 + cpair;
        bv[nf][0] = (HAS_EPI && c < NB) ? bias[c] : 0.f;
        bv[nf][1] = (HAS_EPI && c + 1 < NB) ? bias[c + 1] : 0.f;
    }
#pragma unroll
    for (int mf = 0; mf < 2; mf++) {
#pragma unroll
        for (int h = 0; h < 2; h++) {
            int m = m0 + wm * 32 + mf * 16 + h * 8 + rbase;
            if (m >= M) continue;
#pragma unroll
            for (int nf = 0; nf < 4; nf++) {
                int c = n0 + wn * 32 + nf * 8 + cpair;
                float v0 = d[mf][nf][h * 2 + 0] + bv[nf][0];
                float v1 = d[mf][nf][h * 2 + 1] + bv[nf][1];
                if (HAS_C0) {
                    if (c < ldc0)     v0 += C0[(size_t)m * ldc0 + c];
                    if (c + 1 < ldc0) v1 += C0[(size_t)m * ldc0 + c + 1];
                }
                if (HAS_EPI) { v0 = elu_f(v0); v1 = elu_f(v1); }
                if (OUT_SPLIT) {
                    if (c < ldo) {
                        __nv_bfloat16 h0 = __float2bfloat16(v0);
                        __nv_bfloat16 h1v = __float2bfloat16(v1);
                        __nv_bfloat16 l0 = __float2bfloat16(v0 - __bfloat162float(h0));
                        __nv_bfloat16 l1 = __float2bfloat16(v1 - __bfloat162float(h1v));
                        *(ushort2*)&Oh[(size_t)m * ldo + c] =
                            make_ushort2(__bfloat16_as_ushort(h0), __bfloat16_as_ushort(h1v));
                        *(ushort2*)&Ol[(size_t)m * ldo + c] =
                            make_ushort2(__bfloat16_as_ushort(l0), __bfloat16_as_ushort(l1));
                    }
                } else {
                    if (c < ldo)
                        *(float2*)&Of[(size_t)m * ldo + c] = make_float2(v0, v1);
                }
            }
        }
    }
}

// ---------------- launch ----------------
extern "C" void kernel_launch(void* const* d_in, const int* in_sizes, int n_in,
                              void* d_out, int out_size) {
    const float* x   = (const float*)d_in[0];
    const int*   src = (const int*)d_in[1];
    const int*   dst = (const int*)d_in[2];
    const float* W1  = (const float*)d_in[3];
    const float* b1  = (const float*)d_in[4];
    const float* Wn  = (const float*)d_in[5];
    const float* Ws  = (const float*)d_in[6];
    const float* b2  = (const float*)d_in[7];
    const float* W3  = (const float*)d_in[8];
    const float* b3  = (const float*)d_in[9];
    float* out = (float*)d_out;

    auto sym = [](const void* s) { void* p = nullptr; cudaGetSymbolAddress(&p, s); return p; };
    __nv_bfloat16* aggh = (__nv_bfloat16*)sym(g_aggh);
    __nv_bfloat16* aggl = (__nv_bfloat16*)sym(g_aggl);
    __nv_bfloat16* h1h  = (__nv_bfloat16*)sym(g_h1h);
    __nv_bfloat16* h1l  = (__nv_bfloat16*)sym(g_h1l);
    __nv_bfloat16* h2h  = (__nv_bfloat16*)sym(g_h2h);
    __nv_bfloat16* h2l  = (__nv_bfloat16*)sym(g_h2l);
    float* hWn    = (float*)sym(g_hWn);
    float* neighW = (float*)sym(g_neighWn);
    __nv_bfloat16* B1h  = (__nv_bfloat16*)sym(g_B1h),  *B1l  = (__nv_bfloat16*)sym(g_B1l);
    __nv_bfloat16* BWnh = (__nv_bfloat16*)sym(g_BWnh), *BWnl = (__nv_bfloat16*)sym(g_BWnl);
    __nv_bfloat16* BWsh = (__nv_bfloat16*)sym(g_BWsh), *BWsl = (__nv_bfloat16*)sym(g_BWsl);
    __nv_bfloat16* B3h  = (__nv_bfloat16*)sym(g_B3h),  *B3l  = (__nv_bfloat16*)sym(g_B3l);

    k_zero<<<(NN + 255) / 256, 256>>>();
    k_degrees<<<(EE / 4 + 255) / 256, 256>>>((const int4*)src, (const int4*)dst);
    k_scan_norms<<<SCAN_B, 1024>>>();
    k_fill<<<(EE + 255) / 256, 256>>>(src, dst);
    k_wprep_all<<<(192*128 + 128*160*2 + 64*128 + 255) / 256, 256>>>(W1, Wn, Ws, W3);

    int agg_blocks = (NN * 32 + 255) / 256;
    k_agg1<<<agg_blocks, 256>>>(x);

    int MT = (NN + 127) / 128;  // 391

    // h1 = elu(agg @ W1 + b1) -> bf16 hi/lo [NN, 160]; 3x(128x64) tiles
    k_mm<128, true, false, true><<<dim3(3, MT), 256>>>(
        aggh, aggl, NN, B1h, B1l, b1, D1, nullptr, 0,
        nullptr, h1h, h1l, KP1);

    // hWn = h1 @ Wn -> fp32 [NN, 100]
    k_mm<160, false, false, false><<<dim3(2, MT), 256>>>(
        h1h, h1l, NN, BWnh, BWnl, nullptr, D2, nullptr, 0,
        hWn, nullptr, nullptr, LD2);

    k_agg2<<<agg_blocks, 256>>>();

    // h2 = elu(h1 @ Ws + neighWn + b2) -> bf16 hi/lo [NN, 128]
    k_mm<160, true, true, true><<<dim3(2, MT), 256>>>(
        h1h, h1l, NN, BWsh, BWsl, b2, D2, neighW, LD2,
        nullptr, h2h, h2l, KP2);

    // out = elu(h2 @ W3 + b3) -> fp32 [NN, 64]
    k_mm<128, true, false, false><<<dim3(1, MT), 256>>>(
        h2h, h2l, NN, B3h, B3l, b3, DOUT, nullptr, 0,
        out, nullptr, nullptr, DOUT);
}

// round 12
// speedup vs baseline: 1.5188x; 1.0158x over previous
#include <cuda_runtime.h>
#include <cuda_bf16.h>
#include <math.h>
#include <stdint.h>

#define NN   50000
#define EE   800000
#define DIN  128
#define D1   150
#define KP1  160     // h1 K-padded (row stride)
#define D2   100
#define LD2  100     // fp32 hWn/neighWn stride
#define KP2  128     // h2 K-padded
#define DOUT 64
#define SCAN_B ((NN + 1023) / 1024)

// ---------------- scratch ----------------
__device__ float g_deg_out[NN];
__device__ int   g_deg_in[NN];
__device__ int   g_off[NN + 1];
__device__ int   g_cur[NN];
__device__ int   g_pref[SCAN_B];
__device__ int   g_csr[EE];
__device__ float g_norm_out[NN];
__device__ float g_norm_in[NN];
__device__ float g_invdeg[NN];

__device__ __align__(16) __nv_bfloat16 g_aggh[(size_t)NN * DIN];
__device__ __align__(16) __nv_bfloat16 g_aggl[(size_t)NN * DIN];
__device__ __align__(16) __nv_bfloat16 g_h1h[(size_t)NN * KP1];
__device__ __align__(16) __nv_bfloat16 g_h1l[(size_t)NN * KP1];
__device__ __align__(16) __nv_bfloat16 g_h2h[(size_t)NN * KP2];
__device__ __align__(16) __nv_bfloat16 g_h2l[(size_t)NN * KP2];
__device__ __align__(16) float g_hWn[(size_t)NN * LD2];
__device__ __align__(16) float g_neighWn[(size_t)NN * LD2];

// weights transposed [NPAD, KPAD] bf16 hi/lo  (B1 padded to 192 rows for 3x64 tiling)
__device__ __align__(16) __nv_bfloat16 g_B1h[192 * 128], g_B1l[192 * 128];
__device__ __align__(16) __nv_bfloat16 g_BWnh[128 * 160], g_BWnl[128 * 160];
__device__ __align__(16) __nv_bfloat16 g_BWsh[128 * 160], g_BWsl[128 * 160];
__device__ __align__(16) __nv_bfloat16 g_B3h[64 * 128],  g_B3l[64 * 128];

// fast ELU (MUFU-based; abs err ~1e-7 where exp-1 cancels -> negligible)
__device__ __forceinline__ float elu_f(float v) {
    return v > 0.f ? v : (__expf(v) - 1.f);
}

__device__ __forceinline__ uint32_t smem_u32(const void* p) {
    uint32_t a;
    asm("{ .reg .u64 t; cvta.to.shared.u64 t, %1; cvt.u32.u64 %0, t; }" : "=r"(a) : "l"(p));
    return a;
}
__device__ __forceinline__ void ldsm_x4(uint32_t addr, uint32_t* r) {
    asm volatile("ldmatrix.sync.aligned.m8n8.x4.shared.b16 {%0,%1,%2,%3}, [%4];"
                 : "=r"(r[0]), "=r"(r[1]), "=r"(r[2]), "=r"(r[3]) : "r"(addr));
}
__device__ __forceinline__ void mma_bf16(float* d, const uint32_t* a, const uint32_t* b) {
    asm volatile("mma.sync.aligned.m16n8k16.row.col.f32.bf16.bf16.f32 "
                 "{%0,%1,%2,%3}, {%4,%5,%6,%7}, {%8,%9}, {%0,%1,%2,%3};"
                 : "+f"(d[0]), "+f"(d[1]), "+f"(d[2]), "+f"(d[3])
                 : "r"(a[0]), "r"(a[1]), "r"(a[2]), "r"(a[3]), "r"(b[0]), "r"(b[1]));
}

// ---------------- weight split helper ----------------
__device__ __forceinline__ void wsplit(const float* W, int KB, int NB, int KPAD,
                                       __nv_bfloat16* bh, __nv_bfloat16* bl, int idx) {
    int n = idx / KPAD, k = idx % KPAD;
    float v = (n < NB && k < KB) ? W[(size_t)k * NB + n] : 0.f;
    __nv_bfloat16 hv = __float2bfloat16(v);
    bh[idx] = hv;
    bl[idx] = __float2bfloat16(v - __bfloat162float(hv));
}

// ---------------- merged zero + weight prep (independent early work) -------------
__global__ void k_zero_wprep(const float* __restrict__ W1, const float* __restrict__ Wn,
                             const float* __restrict__ Ws, const float* __restrict__ W3) {
    int i = blockIdx.x * 256 + threadIdx.x;
    if (i < NN) { g_deg_out[i] = 0.f; g_deg_in[i] = 0; }
    if (i < SCAN_B) g_pref[i] = 0;
    const int S1 = 192 * 128, S2 = 128 * 160, S3 = 128 * 160, S4 = 64 * 128;
    if (i < S1) { wsplit(W1, DIN, D1, 128, g_B1h, g_B1l, i); return; }
    i -= S1;
    if (i < S2) { wsplit(Wn, D1, D2, 160, g_BWnh, g_BWnl, i); return; }
    i -= S2;
    if (i < S3) { wsplit(Ws, D1, D2, 160, g_BWsh, g_BWsl, i); return; }
    i -= S3;
    if (i < S4) { wsplit(W3, D2, DOUT, 128, g_B3h, g_B3l, i); return; }
}

// 4 edges/thread via int4 (R7 evidence: beneficial for degrees)
__global__ void k_degrees(const int4* __restrict__ src4, const int4* __restrict__ dst4) {
    int i = blockIdx.x * blockDim.x + threadIdx.x;
    if (i >= EE / 4) return;
    int4 s = src4[i], d = dst4[i];
    atomicAdd(&g_deg_out[s.x], 1.f);
    atomicAdd(&g_deg_out[s.y], 1.f);
    atomicAdd(&g_deg_out[s.z], 1.f);
    atomicAdd(&g_deg_out[s.w], 1.f);
    atomicAdd(&g_deg_in[d.x], 1);
    atomicAdd(&g_deg_in[d.y], 1);
    atomicAdd(&g_deg_in[d.z], 1);
    atomicAdd(&g_deg_in[d.w], 1);
}
__global__ void k_scan_norms() {
    __shared__ int s[1024];
    __shared__ int s_carry;
    int tid = threadIdx.x, b = blockIdx.x;
    int i = b * 1024 + tid;
    if (i < NN) {
        g_norm_out[i] = rsqrtf(fmaxf(g_deg_out[i], 1.f));
        float dmx = fmaxf((float)g_deg_in[i], 1.f);
        g_norm_in[i] = rsqrtf(dmx);
        g_invdeg[i]  = 1.f / dmx;
    }
    int v = (i < NN) ? g_deg_in[i] : 0;
    s[tid] = v;
    __syncthreads();
    for (int off = 1; off < 1024; off <<= 1) {
        int t = (tid >= off) ? s[tid - off] : 0;
        __syncthreads();
        s[tid] += t;
        __syncthreads();
    }
    if (tid == 1023) {
        int prev = 0;
        if (b > 0) {
            int pv;
            do { pv = atomicAdd(&g_pref[b - 1], 0); } while (pv == 0);
            prev = pv - 1;
        }
        atomicExch(&g_pref[b], prev + s[1023] + 1);
        s_carry = prev;
    }
    __syncthreads();
    int carry = s_carry;
    if (i < NN) {
        g_off[i + 1] = s[tid] + carry;
        g_cur[i] = s[tid] + carry - v;   // exclusive prefix: fill writes direct
    }
    if (i == 0) g_off[0] = 0;
}
// scalar fill: max TLP hides atomic->store chain latency (R6 evidence)
__global__ void k_fill(const int* __restrict__ src, const int* __restrict__ dst) {
    int e = blockIdx.x * blockDim.x + threadIdx.x;
    if (e >= EE) return;
    int d = dst[e];
    int p = atomicAdd(&g_cur[d], 1);
    g_csr[p] = src[e];
}

// ---------------- layer-1 aggregation -> bf16 hi/lo ----------------
__global__ void k_agg1(const float* __restrict__ x) {
    int w    = (blockIdx.x * blockDim.x + threadIdx.x) >> 5;
    int lane = threadIdx.x & 31;
    if (w >= NN) return;
    int beg = g_off[w], end = g_off[w + 1];
    const float4* X = (const float4*)x;
    float4 acc = make_float4(0.f, 0.f, 0.f, 0.f);
    int j = beg;
    for (; j + 3 < end; j += 4) {
        int s0 = g_csr[j], s1 = g_csr[j + 1], s2 = g_csr[j + 2], s3 = g_csr[j + 3];
        float w0 = g_norm_out[s0], w1 = g_norm_out[s1];
        float w2 = g_norm_out[s2], w3 = g_norm_out[s3];
        float4 v0 = X[(size_t)s0 * 32 + lane];
        float4 v1 = X[(size_t)s1 * 32 + lane];
        float4 v2 = X[(size_t)s2 * 32 + lane];
        float4 v3 = X[(size_t)s3 * 32 + lane];
        acc.x += v0.x * w0 + v1.x * w1 + v2.x * w2 + v3.x * w3;
        acc.y += v0.y * w0 + v1.y * w1 + v2.y * w2 + v3.y * w3;
        acc.z += v0.z * w0 + v1.z * w1 + v2.z * w2 + v3.z * w3;
        acc.w += v0.w * w0 + v1.w * w1 + v2.w * w2 + v3.w * w3;
    }
    for (; j < end; j++) {
        int s0 = g_csr[j];
        float w0 = g_norm_out[s0];
        float4 v0 = X[(size_t)s0 * 32 + lane];
        acc.x += v0.x * w0; acc.y += v0.y * w0; acc.z += v0.z * w0; acc.w += v0.w * w0;
    }
    float ni = g_norm_in[w];
    float v[4] = { acc.x * ni, acc.y * ni, acc.z * ni, acc.w * ni };
    __nv_bfloat16 hv[4], lv[4];
#pragma unroll
    for (int q = 0; q < 4; q++) {
        hv[q] = __float2bfloat16(v[q]);
        lv[q] = __float2bfloat16(v[q] - __bfloat162float(hv[q]));
    }
    *(ushort4*)&g_aggh[(size_t)w * DIN + lane * 4] =
        make_ushort4(__bfloat16_as_ushort(hv[0]), __bfloat16_as_ushort(hv[1]),
                     __bfloat16_as_ushort(hv[2]), __bfloat16_as_ushort(hv[3]));
    *(ushort4*)&g_aggl[(size_t)w * DIN + lane * 4] =
        make_ushort4(__bfloat16_as_ushort(lv[0]), __bfloat16_as_ushort(lv[1]),
                     __bfloat16_as_ushort(lv[2]), __bfloat16_as_ushort(lv[3]));
}

// ---------------- layer-2 aggregation of hWn (fp32, 100 cols = 25 float4) --------
__global__ void k_agg2() {
    int w    = (blockIdx.x * blockDim.x + threadIdx.x) >> 5;
    int lane = threadIdx.x & 31;
    if (w >= NN) return;
    if (lane >= LD2 / 4) return;
    int beg = g_off[w], end = g_off[w + 1];
    const float4* X = (const float4*)g_hWn;
    float4 acc = make_float4(0.f, 0.f, 0.f, 0.f);
    int j = beg;
    for (; j + 1 < end; j += 2) {
        int s0 = g_csr[j], s1 = g_csr[j + 1];
        float4 v0 = X[(size_t)s0 * (LD2 / 4) + lane];
        float4 v1 = X[(size_t)s1 * (LD2 / 4) + lane];
        acc.x += v0.x + v1.x; acc.y += v0.y + v1.y;
        acc.z += v0.z + v1.z; acc.w += v0.w + v1.w;
    }
    if (j < end) {
        int s0 = g_csr[j];
        float4 v0 = X[(size_t)s0 * (LD2 / 4) + lane];
        acc.x += v0.x; acc.y += v0.y; acc.z += v0.z; acc.w += v0.w;
    }
    float inv = g_invdeg[w];
    acc.x *= inv; acc.y *= inv; acc.z *= inv; acc.w *= inv;
    ((float4*)g_neighWn)[(size_t)w * (LD2 / 4) + lane] = acc;
}

// ---------------- fused 3-term bf16-split GEMM, DOUBLE-BUFFERED smem -------------
// D = Ahi.Bhi + Ahi.Blo + Alo.Bhi ; block 128M x 64N, 8 warps (4M x 2N)
// one __syncthreads per k32 chunk; STS-of-next overlaps LDSM/MMA-of-current.
template<int KPAD, bool HAS_EPI, bool HAS_C0, bool OUT_SPLIT>
__global__ void __launch_bounds__(256, 2) k_mm(
    const __nv_bfloat16* __restrict__ Ah, const __nv_bfloat16* __restrict__ Al,
    int M,
    const __nv_bfloat16* __restrict__ Bh, const __nv_bfloat16* __restrict__ Bl,
    const float* __restrict__ bias, int NB,
    const float* __restrict__ C0, int ldc0,
    float* __restrict__ Of, __nv_bfloat16* __restrict__ Oh,
    __nv_bfloat16* __restrict__ Ol, int ldo)
{
    constexpr int NT  = 64;
    constexpr int NC  = KPAD / 32;
    constexpr int ATB = 128 * 80;
    constexpr int BTB = NT * 80;
    // layout: [AH0][AH1][AL0][AL1][BH0][BH1][BL0][BL1] = 4*ATB + 4*BTB = 61440 B
    extern __shared__ __align__(16) char smem[];
    const int O_AL = 2 * ATB;
    const int O_BH = 4 * ATB;
    const int O_BL = 4 * ATB + 2 * BTB;

    int t = threadIdx.x, lane = t & 31, wid = t >> 5;
    int wm = wid & 3, wn = wid >> 2;
    int m0 = blockIdx.y * 128, n0 = blockIdx.x * NT;

    // warp-uniform fragment activity
    int cw = n0 + wn * 32;
    bool act0 = (cw + 0)  < NB;
    bool act1 = (cw + 8)  < NB;
    bool act2 = (cw + 16) < NB;
    bool act3 = (cw + 24) < NB;
    bool act23 = act2 | act3;

    uint32_t sbase = smem_u32(smem);
    int tile = lane >> 3, trow = lane & 7;
    uint32_t aOff = (uint32_t)(((wm * 32 + (tile & 1) * 8 + trow) * 40 + (tile >> 1) * 8) * 2);
    uint32_t bOff = (uint32_t)(((wn * 32 + (tile >> 1) * 8 + trow) * 40 + (tile & 1) * 8) * 2);

    float d[2][4][4];
#pragma unroll
    for (int i = 0; i < 2; i++)
#pragma unroll
        for (int j = 0; j < 4; j++)
#pragma unroll
            for (int q = 0; q < 4; q++) d[i][j][q] = 0.f;

    uint4 rah[2], ral[2];
    uint4 rbh, rbl, rbh2, rbl2;
    int arow = t >> 1, ahalf = t & 1, brow = t >> 1, bq = t & 1;
    int mload = m0 + arow; if (mload >= M) mload = M - 1;

    auto ldregs = [&](int cc) {
        int k0 = cc * 32;
        const char* ah = (const char*)(Ah + (size_t)mload * KPAD + k0) + ahalf * 32;
        const char* al = (const char*)(Al + (size_t)mload * KPAD + k0) + ahalf * 32;
        rah[0] = *(const uint4*)ah;  rah[1] = *(const uint4*)(ah + 16);
        ral[0] = *(const uint4*)al;  ral[1] = *(const uint4*)(al + 16);
        if (t < NT * 2) {
            int n = n0 + brow;
            const char* bh = (const char*)(Bh + (size_t)n * KPAD + k0) + bq * 32;
            const char* bl = (const char*)(Bl + (size_t)n * KPAD + k0) + bq * 32;
            rbh  = *(const uint4*)bh;  rbh2 = *(const uint4*)(bh + 16);
            rbl  = *(const uint4*)bl;  rbl2 = *(const uint4*)(bl + 16);
        }
    };
    auto store_smem = [&](int buf) {
        char* pah = smem + buf * ATB + arow * 80 + ahalf * 32;
        char* pal = smem + O_AL + buf * ATB + arow * 80 + ahalf * 32;
        *(uint4*)pah = rah[0]; *(uint4*)(pah + 16) = rah[1];
        *(uint4*)pal = ral[0]; *(uint4*)(pal + 16) = ral[1];
        if (t < NT * 2) {
            char* pbh = smem + O_BH + buf * BTB + brow * 80 + bq * 32;
            char* pbl = smem + O_BL + buf * BTB + brow * 80 + bq * 32;
            *(uint4*)pbh = rbh; *(uint4*)(pbh + 16) = rbh2;
            *(uint4*)pbl = rbl; *(uint4*)(pbl + 16) = rbl2;
        }
    };

    ldregs(0);
    store_smem(0);
    __syncthreads();
#pragma unroll 1
    for (int cc = 0; cc < NC; cc++) {
        int buf = cc & 1;
        if (cc + 1 < NC) ldregs(cc + 1);
        uint32_t aH_addr = sbase + buf * ATB + aOff;
        uint32_t aL_addr = sbase + O_AL + buf * ATB + aOff;
        uint32_t bH_addr = sbase + O_BH + buf * BTB + bOff;
        uint32_t bL_addr = sbase + O_BL + buf * BTB + bOff;
#pragma unroll
        for (int kk = 0; kk < 2; kk++) {
            uint32_t aH[2][4], aL[2][4], bH[2][4], bL[2][4];
            ldsm_x4(aH_addr + kk * 32, aH[0]);
            ldsm_x4(aH_addr + 1280 + kk * 32, aH[1]);
            ldsm_x4(aL_addr + kk * 32, aL[0]);
            ldsm_x4(aL_addr + 1280 + kk * 32, aL[1]);
            ldsm_x4(bH_addr + kk * 32, bH[0]);
            ldsm_x4(bL_addr + kk * 32, bL[0]);
            if (act23) {
                ldsm_x4(bH_addr + 1280 + kk * 32, bH[1]);
                ldsm_x4(bL_addr + 1280 + kk * 32, bL[1]);
            }
#pragma unroll
            for (int mf = 0; mf < 2; mf++) {
#pragma unroll
                for (int nf = 0; nf < 4; nf++) {
                    bool act = (nf == 0) ? act0 : (nf == 1) ? act1 : (nf == 2) ? act2 : act3;
                    if (act) {
                        uint32_t* bhp = &bH[nf >> 1][(nf & 1) * 2];
                        uint32_t* blp = &bL[nf >> 1][(nf & 1) * 2];
                        mma_bf16(d[mf][nf], aH[mf], bhp);
                        mma_bf16(d[mf][nf], aH[mf], blp);
                        mma_bf16(d[mf][nf], aL[mf], bhp);
                    }
                }
            }
        }
        if (cc + 1 < NC) store_smem(buf ^ 1);
        __syncthreads();
    }

    // ---------------- epilogue ----------------
    int rbase = lane >> 2, cpair = (lane & 3) * 2;
    float bv[4][2];
#pragma unroll
    for (int nf = 0; nf < 4; nf++) {
        int c = n0 + wn * 32 + nf * 8 + cpair;
        bv[nf][0] = (HAS_EPI && c < NB) ? bias[c] : 0.f;
        bv[nf][1] = (HAS_EPI && c + 1 < NB) ? bias[c + 1] : 0.f;
    }
#pragma unroll
    for (int mf = 0; mf < 2; mf++) {
#pragma unroll
        for (int h = 0; h < 2; h++) {
            int m = m0 + wm * 32 + mf * 16 + h * 8 + rbase;
            if (m >= M) continue;
#pragma unroll
            for (int nf = 0; nf < 4; nf++) {
                int c = n0 + wn * 32 + nf * 8 + cpair;
                float v0 = d[mf][nf][h * 2 + 0] + bv[nf][0];
                float v1 = d[mf][nf][h * 2 + 1] + bv[nf][1];
                if (HAS_C0) {
                    if (c < ldc0)     v0 += C0[(size_t)m * ldc0 + c];
                    if (c + 1 < ldc0) v1 += C0[(size_t)m * ldc0 + c + 1];
                }
                if (HAS_EPI) { v0 = elu_f(v0); v1 = elu_f(v1); }
                if (OUT_SPLIT) {
                    if (c < ldo) {
                        __nv_bfloat16 h0 = __float2bfloat16(v0);
                        __nv_bfloat16 h1v = __float2bfloat16(v1);
                        __nv_bfloat16 l0 = __float2bfloat16(v0 - __bfloat162float(h0));
                        __nv_bfloat16 l1 = __float2bfloat16(v1 - __bfloat162float(h1v));
                        *(ushort2*)&Oh[(size_t)m * ldo + c] =
                            make_ushort2(__bfloat16_as_ushort(h0), __bfloat16_as_ushort(h1v));
                        *(ushort2*)&Ol[(size_t)m * ldo + c] =
                            make_ushort2(__bfloat16_as_ushort(l0), __bfloat16_as_ushort(l1));
                    }
                } else {
                    if (c < ldo)
                        *(float2*)&Of[(size_t)m * ldo + c] = make_float2(v0, v1);
                }
            }
        }
    }
}

// ---------------- launch ----------------
extern "C" void kernel_launch(void* const* d_in, const int* in_sizes, int n_in,
                              void* d_out, int out_size) {
    const float* x   = (const float*)d_in[0];
    const int*   src = (const int*)d_in[1];
    const int*   dst = (const int*)d_in[2];
    const float* W1  = (const float*)d_in[3];
    const float* b1  = (const float*)d_in[4];
    const float* Wn  = (const float*)d_in[5];
    const float* Ws  = (const float*)d_in[6];
    const float* b2  = (const float*)d_in[7];
    const float* W3  = (const float*)d_in[8];
    const float* b3  = (const float*)d_in[9];
    float* out = (float*)d_out;

    auto sym = [](const void* s) { void* p = nullptr; cudaGetSymbolAddress(&p, s); return p; };
    __nv_bfloat16* aggh = (__nv_bfloat16*)sym(g_aggh);
    __nv_bfloat16* aggl = (__nv_bfloat16*)sym(g_aggl);
    __nv_bfloat16* h1h  = (__nv_bfloat16*)sym(g_h1h);
    __nv_bfloat16* h1l  = (__nv_bfloat16*)sym(g_h1l);
    __nv_bfloat16* h2h  = (__nv_bfloat16*)sym(g_h2h);
    __nv_bfloat16* h2l  = (__nv_bfloat16*)sym(g_h2l);
    float* hWn    = (float*)sym(g_hWn);
    float* neighW = (float*)sym(g_neighWn);
    __nv_bfloat16* B1h  = (__nv_bfloat16*)sym(g_B1h),  *B1l  = (__nv_bfloat16*)sym(g_B1l);
    __nv_bfloat16* BWnh = (__nv_bfloat16*)sym(g_BWnh), *BWnl = (__nv_bfloat16*)sym(g_BWnl);
    __nv_bfloat16* BWsh = (__nv_bfloat16*)sym(g_BWsh), *BWsl = (__nv_bfloat16*)sym(g_BWsl);
    __nv_bfloat16* B3h  = (__nv_bfloat16*)sym(g_B3h),  *B3l  = (__nv_bfloat16*)sym(g_B3l);

    const int SMEMSZ = 61440;
    cudaFuncSetAttribute(k_mm<128, true,  false, true >, cudaFuncAttributeMaxDynamicSharedMemorySize, SMEMSZ);
    cudaFuncSetAttribute(k_mm<160, false, false, false>, cudaFuncAttributeMaxDynamicSharedMemorySize, SMEMSZ);
    cudaFuncSetAttribute(k_mm<160, true,  true,  true >, cudaFuncAttributeMaxDynamicSharedMemorySize, SMEMSZ);
    cudaFuncSetAttribute(k_mm<128, true,  false, false>, cudaFuncAttributeMaxDynamicSharedMemorySize, SMEMSZ);

    // merged zero + weight prep (covers max(NN, wprep total) indices)
    const int WPT = 192 * 128 + 128 * 160 * 2 + 64 * 128;  // 96768 > NN
    k_zero_wprep<<<(WPT + 255) / 256, 256>>>(W1, Wn, Ws, W3);
    k_degrees<<<(EE / 4 + 255) / 256, 256>>>((const int4*)src, (const int4*)dst);
    k_scan_norms<<<SCAN_B, 1024>>>();
    k_fill<<<(EE + 255) / 256, 256>>>(src, dst);

    int agg_blocks = (NN * 32 + 255) / 256;
    k_agg1<<<agg_blocks, 256>>>(x);

    int MT = (NN + 127) / 128;  // 391

    // h1 = elu(agg @ W1 + b1) -> bf16 hi/lo [NN, 160]; 3x(128x64) tiles
    k_mm<128, true, false, true><<<dim3(3, MT), 256, SMEMSZ>>>(
        aggh, aggl, NN, B1h, B1l, b1, D1, nullptr, 0,
        nullptr, h1h, h1l, KP1);

    // hWn = h1 @ Wn -> fp32 [NN, 100]
    k_mm<160, false, false, false><<<dim3(2, MT), 256, SMEMSZ>>>(
        h1h, h1l, NN, BWnh, BWnl, nullptr, D2, nullptr, 0,
        hWn, nullptr, nullptr, LD2);

    k_agg2<<<agg_blocks, 256>>>();

    // h2 = elu(h1 @ Ws + neighWn + b2) -> bf16 hi/lo [NN, 128]
    k_mm<160, true, true, true><<<dim3(2, MT), 256, SMEMSZ>>>(
        h1h, h1l, NN, BWsh, BWsl, b2, D2, neighW, LD2,
        nullptr, h2h, h2l, KP2);

    // out = elu(h2 @ W3 + b3) -> fp32 [NN, 64]
    k_mm<128, true, false, false><<<dim3(1, MT), 256, SMEMSZ>>>(
        h2h, h2l, NN, B3h, B3l, b3, DOUT, nullptr, 0,
        out, nullptr, nullptr, DOUT);
}

// round 14
// speedup vs baseline: 1.5712x; 1.0345x over previous
#include <cuda_runtime.h>
#include <cuda_bf16.h>
#include <math.h>
#include <stdint.h>

#define NN   50000
#define EE   800000
#define DIN  128
#define D1   150
#define KP1  160     // h1 K-padded (row stride)
#define D2   100
#define LD2  100     // fp32 hWn/h2pre stride
#define KP2  128     // h2 K-padded
#define DOUT 64
#define SCAN_B ((NN + 1023) / 1024)

// ---------------- scratch ----------------
__device__ float g_deg_out[NN];
__device__ int   g_deg_in[NN];
__device__ int   g_off[NN + 1];
__device__ int   g_cur[NN];
__device__ int   g_pref[SCAN_B];
__device__ int   g_csr[EE];
__device__ float g_norm_out[NN];
__device__ float g_norm_in[NN];
__device__ float g_invdeg[NN];

__device__ __align__(16) __nv_bfloat16 g_aggh[(size_t)NN * DIN];
__device__ __align__(16) __nv_bfloat16 g_aggl[(size_t)NN * DIN];
__device__ __align__(16) __nv_bfloat16 g_h1h[(size_t)NN * KP1];
__device__ __align__(16) __nv_bfloat16 g_h1l[(size_t)NN * KP1];
__device__ __align__(16) __nv_bfloat16 g_h2h[(size_t)NN * KP2];
__device__ __align__(16) __nv_bfloat16 g_h2l[(size_t)NN * KP2];
__device__ __align__(16) float g_hWn[(size_t)NN * LD2];
__device__ __align__(16) float g_h2pre[(size_t)NN * LD2];

// weights transposed [NPAD, KPAD] bf16 hi/lo  (B1 padded to 192 rows for 3x64 tiling)
__device__ __align__(16) __nv_bfloat16 g_B1h[192 * 128], g_B1l[192 * 128];
__device__ __align__(16) __nv_bfloat16 g_BWnh[128 * 160], g_BWnl[128 * 160];
__device__ __align__(16) __nv_bfloat16 g_BWsh[128 * 160], g_BWsl[128 * 160];
__device__ __align__(16) __nv_bfloat16 g_B3h[64 * 128],  g_B3l[64 * 128];

// fast ELU (MUFU-based; abs err ~1e-7 where exp-1 cancels -> negligible)
__device__ __forceinline__ float elu_f(float v) {
    return v > 0.f ? v : (__expf(v) - 1.f);
}

__device__ __forceinline__ uint32_t smem_u32(const void* p) {
    uint32_t a;
    asm("{ .reg .u64 t; cvta.to.shared.u64 t, %1; cvt.u32.u64 %0, t; }" : "=r"(a) : "l"(p));
    return a;
}
__device__ __forceinline__ void ldsm_x4(uint32_t addr, uint32_t* r) {
    asm volatile("ldmatrix.sync.aligned.m8n8.x4.shared.b16 {%0,%1,%2,%3}, [%4];"
                 : "=r"(r[0]), "=r"(r[1]), "=r"(r[2]), "=r"(r[3]) : "r"(addr));
}
__device__ __forceinline__ void mma_bf16(float* d, const uint32_t* a, const uint32_t* b) {
    asm volatile("mma.sync.aligned.m16n8k16.row.col.f32.bf16.bf16.f32 "
                 "{%0,%1,%2,%3}, {%4,%5,%6,%7}, {%8,%9}, {%0,%1,%2,%3};"
                 : "+f"(d[0]), "+f"(d[1]), "+f"(d[2]), "+f"(d[3])
                 : "r"(a[0]), "r"(a[1]), "r"(a[2]), "r"(a[3]), "r"(b[0]), "r"(b[1]));
}

// ---------------- weight split helper ----------------
__device__ __forceinline__ void wsplit(const float* W, int KB, int NB, int KPAD,
                                       __nv_bfloat16* bh, __nv_bfloat16* bl, int idx) {
    int n = idx / KPAD, k = idx % KPAD;
    float v = (n < NB && k < KB) ? W[(size_t)k * NB + n] : 0.f;
    __nv_bfloat16 hv = __float2bfloat16(v);
    bh[idx] = hv;
    bl[idx] = __float2bfloat16(v - __bfloat162float(hv));
}

// ---------------- merged zero + weight prep ----------------
__global__ void k_zero_wprep(const float* __restrict__ W1, const float* __restrict__ Wn,
                             const float* __restrict__ Ws, const float* __restrict__ W3) {
    int i = blockIdx.x * 256 + threadIdx.x;
    if (i < NN) { g_deg_out[i] = 0.f; g_deg_in[i] = 0; }
    if (i < SCAN_B) g_pref[i] = 0;
    const int S1 = 192 * 128, S2 = 128 * 160, S3 = 128 * 160, S4 = 64 * 128;
    if (i < S1) { wsplit(W1, DIN, D1, 128, g_B1h, g_B1l, i); return; }
    i -= S1;
    if (i < S2) { wsplit(Wn, D1, D2, 160, g_BWnh, g_BWnl, i); return; }
    i -= S2;
    if (i < S3) { wsplit(Ws, D1, D2, 160, g_BWsh, g_BWsl, i); return; }
    i -= S3;
    if (i < S4) { wsplit(W3, D2, DOUT, 128, g_B3h, g_B3l, i); return; }
}

__global__ void k_degrees(const int4* __restrict__ src4, const int4* __restrict__ dst4) {
    int i = blockIdx.x * blockDim.x + threadIdx.x;
    if (i >= EE / 4) return;
    int4 s = src4[i], d = dst4[i];
    atomicAdd(&g_deg_out[s.x], 1.f);
    atomicAdd(&g_deg_out[s.y], 1.f);
    atomicAdd(&g_deg_out[s.z], 1.f);
    atomicAdd(&g_deg_out[s.w], 1.f);
    atomicAdd(&g_deg_in[d.x], 1);
    atomicAdd(&g_deg_in[d.y], 1);
    atomicAdd(&g_deg_in[d.z], 1);
    atomicAdd(&g_deg_in[d.w], 1);
}
__global__ void k_scan_norms() {
    __shared__ int s[1024];
    __shared__ int s_carry;
    int tid = threadIdx.x, b = blockIdx.x;
    int i = b * 1024 + tid;
    if (i < NN) {
        g_norm_out[i] = rsqrtf(fmaxf(g_deg_out[i], 1.f));
        float dmx = fmaxf((float)g_deg_in[i], 1.f);
        g_norm_in[i] = rsqrtf(dmx);
        g_invdeg[i]  = 1.f / dmx;
    }
    int v = (i < NN) ? g_deg_in[i] : 0;
    s[tid] = v;
    __syncthreads();
    for (int off = 1; off < 1024; off <<= 1) {
        int t = (tid >= off) ? s[tid - off] : 0;
        __syncthreads();
        s[tid] += t;
        __syncthreads();
    }
    if (tid == 1023) {
        int prev = 0;
        if (b > 0) {
            int pv;
            do { pv = atomicAdd(&g_pref[b - 1], 0); } while (pv == 0);
            prev = pv - 1;
        }
        atomicExch(&g_pref[b], prev + s[1023] + 1);
        s_carry = prev;
    }
    __syncthreads();
    int carry = s_carry;
    if (i < NN) {
        g_off[i + 1] = s[tid] + carry;
        g_cur[i] = s[tid] + carry - v;   // exclusive prefix: fill writes direct
    }
    if (i == 0) g_off[0] = 0;
}
__global__ void k_fill(const int* __restrict__ src, const int* __restrict__ dst) {
    int e = blockIdx.x * blockDim.x + threadIdx.x;
    if (e >= EE) return;
    int d = dst[e];
    int p = atomicAdd(&g_cur[d], 1);
    g_csr[p] = src[e];
}

// ---------------- layer-1 aggregation -> bf16 hi/lo ----------------
__global__ void k_agg1(const float* __restrict__ x) {
    int w    = (blockIdx.x * blockDim.x + threadIdx.x) >> 5;
    int lane = threadIdx.x & 31;
    if (w >= NN) return;
    int beg = g_off[w], end = g_off[w + 1];
    const float4* X = (const float4*)x;
    float4 acc = make_float4(0.f, 0.f, 0.f, 0.f);
    int j = beg;
    for (; j + 3 < end; j += 4) {
        int s0 = g_csr[j], s1 = g_csr[j + 1], s2 = g_csr[j + 2], s3 = g_csr[j + 3];
        float w0 = g_norm_out[s0], w1 = g_norm_out[s1];
        float w2 = g_norm_out[s2], w3 = g_norm_out[s3];
        float4 v0 = X[(size_t)s0 * 32 + lane];
        float4 v1 = X[(size_t)s1 * 32 + lane];
        float4 v2 = X[(size_t)s2 * 32 + lane];
        float4 v3 = X[(size_t)s3 * 32 + lane];
        acc.x += v0.x * w0 + v1.x * w1 + v2.x * w2 + v3.x * w3;
        acc.y += v0.y * w0 + v1.y * w1 + v2.y * w2 + v3.y * w3;
        acc.z += v0.z * w0 + v1.z * w1 + v2.z * w2 + v3.z * w3;
        acc.w += v0.w * w0 + v1.w * w1 + v2.w * w2 + v3.w * w3;
    }
    for (; j < end; j++) {
        int s0 = g_csr[j];
        float w0 = g_norm_out[s0];
        float4 v0 = X[(size_t)s0 * 32 + lane];
        acc.x += v0.x * w0; acc.y += v0.y * w0; acc.z += v0.z * w0; acc.w += v0.w * w0;
    }
    float ni = g_norm_in[w];
    float v[4] = { acc.x * ni, acc.y * ni, acc.z * ni, acc.w * ni };
    __nv_bfloat16 hv[4], lv[4];
#pragma unroll
    for (int q = 0; q < 4; q++) {
        hv[q] = __float2bfloat16(v[q]);
        lv[q] = __float2bfloat16(v[q] - __bfloat162float(hv[q]));
    }
    *(ushort4*)&g_aggh[(size_t)w * DIN + lane * 4] =
        make_ushort4(__bfloat16_as_ushort(hv[0]), __bfloat16_as_ushort(hv[1]),
                     __bfloat16_as_ushort(hv[2]), __bfloat16_as_ushort(hv[3]));
    *(ushort4*)&g_aggl[(size_t)w * DIN + lane * 4] =
        make_ushort4(__bfloat16_as_ushort(lv[0]), __bfloat16_as_ushort(lv[1]),
                     __bfloat16_as_ushort(lv[2]), __bfloat16_as_ushort(lv[3]));
}

// ---- fused SAGE tail: h2 = elu(h2pre + mean-agg(hWn)) -> bf16 hi/lo [NN,128] ----
__global__ void k_agg2p() {
    int w    = (blockIdx.x * blockDim.x + threadIdx.x) >> 5;
    int lane = threadIdx.x & 31;
    if (w >= NN) return;
    float4 acc = make_float4(0.f, 0.f, 0.f, 0.f);
    if (lane < LD2 / 4) {
        int beg = g_off[w], end = g_off[w + 1];
        const float4* X = (const float4*)g_hWn;
        int j = beg;
        for (; j + 1 < end; j += 2) {
            int s0 = g_csr[j], s1 = g_csr[j + 1];
            float4 v0 = X[(size_t)s0 * (LD2 / 4) + lane];
            float4 v1 = X[(size_t)s1 * (LD2 / 4) + lane];
            acc.x += v0.x + v1.x; acc.y += v0.y + v1.y;
            acc.z += v0.z + v1.z; acc.w += v0.w + v1.w;
        }
        if (j < end) {
            int s0 = g_csr[j];
            float4 v0 = X[(size_t)s0 * (LD2 / 4) + lane];
            acc.x += v0.x; acc.y += v0.y; acc.z += v0.z; acc.w += v0.w;
        }
        float inv = g_invdeg[w];
        float4 p = ((const float4*)g_h2pre)[(size_t)w * (LD2 / 4) + lane];
        acc.x = elu_f(p.x + acc.x * inv);
        acc.y = elu_f(p.y + acc.y * inv);
        acc.z = elu_f(p.z + acc.z * inv);
        acc.w = elu_f(p.w + acc.w * inv);
    }
    float v[4] = { acc.x, acc.y, acc.z, acc.w };
    __nv_bfloat16 hv[4], lv[4];
#pragma unroll
    for (int q = 0; q < 4; q++) {
        hv[q] = __float2bfloat16(v[q]);
        lv[q] = __float2bfloat16(v[q] - __bfloat162float(hv[q]));
    }
    *(ushort4*)&g_h2h[(size_t)w * KP2 + lane * 4] =
        make_ushort4(__bfloat16_as_ushort(hv[0]), __bfloat16_as_ushort(hv[1]),
                     __bfloat16_as_ushort(hv[2]), __bfloat16_as_ushort(hv[3]));
    *(ushort4*)&g_h2l[(size_t)w * KP2 + lane * 4] =
        make_ushort4(__bfloat16_as_ushort(lv[0]), __bfloat16_as_ushort(lv[1]),
                     __bfloat16_as_ushort(lv[2]), __bfloat16_as_ushort(lv[3]));
}

// ---------------- fused 3-term bf16-split GEMM, double-buffered ----------------
template<int KPAD, bool HAS_EPI, bool OUT_SPLIT>
__global__ void __launch_bounds__(256, 2) k_mm(
    const __nv_bfloat16* __restrict__ Ah, const __nv_bfloat16* __restrict__ Al,
    int M,
    const __nv_bfloat16* __restrict__ Bh, const __nv_bfloat16* __restrict__ Bl,
    const float* __restrict__ bias, int NB,
    float* __restrict__ Of, __nv_bfloat16* __restrict__ Oh,
    __nv_bfloat16* __restrict__ Ol, int ldo)
{
    constexpr int NT  = 64;
    constexpr int NC  = KPAD / 32;
    constexpr int ATB = 128 * 80;
    constexpr int BTB = NT * 80;
    extern __shared__ __align__(16) char smem[];
    const int O_AL = 2 * ATB;
    const int O_BH = 4 * ATB;
    const int O_BL = 4 * ATB + 2 * BTB;

    int t = threadIdx.x, lane = t & 31, wid = t >> 5;
    int wm = wid & 3, wn = wid >> 2;
    int m0 = blockIdx.y * 128, n0 = blockIdx.x * NT;

    int cw = n0 + wn * 32;
    bool act0 = (cw + 0)  < NB;
    bool act1 = (cw + 8)  < NB;
    bool act2 = (cw + 16) < NB;
    bool act3 = (cw + 24) < NB;
    bool act23 = act2 | act3;

    uint32_t sbase = smem_u32(smem);
    int tile = lane >> 3, trow = lane & 7;
    uint32_t aOff = (uint32_t)(((wm * 32 + (tile & 1) * 8 + trow) * 40 + (tile >> 1) * 8) * 2);
    uint32_t bOff = (uint32_t)(((wn * 32 + (tile >> 1) * 8 + trow) * 40 + (tile & 1) * 8) * 2);

    float d[2][4][4];
#pragma unroll
    for (int i = 0; i < 2; i++)
#pragma unroll
        for (int j = 0; j < 4; j++)
#pragma unroll
            for (int q = 0; q < 4; q++) d[i][j][q] = 0.f;

    uint4 rah[2], ral[2];
    uint4 rbh, rbl, rbh2, rbl2;
    int arow = t >> 1, ahalf = t & 1, brow = t >> 1, bq = t & 1;
    int mload = m0 + arow; if (mload >= M) mload = M - 1;

    auto ldregs = [&](int cc) {
        int k0 = cc * 32;
        const char* ah = (const char*)(Ah + (size_t)mload * KPAD + k0) + ahalf * 32;
        const char* al = (const char*)(Al + (size_t)mload * KPAD + k0) + ahalf * 32;
        rah[0] = *(const uint4*)ah;  rah[1] = *(const uint4*)(ah + 16);
        ral[0] = *(const uint4*)al;  ral[1] = *(const uint4*)(al + 16);
        if (t < NT * 2) {
            int n = n0 + brow;
            const char* bh = (const char*)(Bh + (size_t)n * KPAD + k0) + bq * 32;
            const char* bl = (const char*)(Bl + (size_t)n * KPAD + k0) + bq * 32;
            rbh  = *(const uint4*)bh;  rbh2 = *(const uint4*)(bh + 16);
            rbl  = *(const uint4*)bl;  rbl2 = *(const uint4*)(bl + 16);
        }
    };
    auto store_smem = [&](int buf) {
        char* pah = smem + buf * ATB + arow * 80 + ahalf * 32;
        char* pal = smem + O_AL + buf * ATB + arow * 80 + ahalf * 32;
        *(uint4*)pah = rah[0]; *(uint4*)(pah + 16) = rah[1];
        *(uint4*)pal = ral[0]; *(uint4*)(pal + 16) = ral[1];
        if (t < NT * 2) {
            char* pbh = smem + O_BH + buf * BTB + brow * 80 + bq * 32;
            char* pbl = smem + O_BL + buf * BTB + brow * 80 + bq * 32;
            *(uint4*)pbh = rbh; *(uint4*)(pbh + 16) = rbh2;
            *(uint4*)pbl = rbl; *(uint4*)(pbl + 16) = rbl2;
        }
    };

    ldregs(0);
    store_smem(0);
    __syncthreads();
#pragma unroll 1
    for (int cc = 0; cc < NC; cc++) {
        int buf = cc & 1;
        if (cc + 1 < NC) ldregs(cc + 1);
        uint32_t aH_addr = sbase + buf * ATB + aOff;
        uint32_t aL_addr = sbase + O_AL + buf * ATB + aOff;
        uint32_t bH_addr = sbase + O_BH + buf * BTB + bOff;
        uint32_t bL_addr = sbase + O_BL + buf * BTB + bOff;
#pragma unroll
        for (int kk = 0; kk < 2; kk++) {
            uint32_t aH[2][4], aL[2][4], bH[2][4], bL[2][4];
            ldsm_x4(aH_addr + kk * 32, aH[0]);
            ldsm_x4(aH_addr + 1280 + kk * 32, aH[1]);
            ldsm_x4(aL_addr + kk * 32, aL[0]);
            ldsm_x4(aL_addr + 1280 + kk * 32, aL[1]);
            ldsm_x4(bH_addr + kk * 32, bH[0]);
            ldsm_x4(bL_addr + kk * 32, bL[0]);
            if (act23) {
                ldsm_x4(bH_addr + 1280 + kk * 32, bH[1]);
                ldsm_x4(bL_addr + 1280 + kk * 32, bL[1]);
            }
#pragma unroll
            for (int mf = 0; mf < 2; mf++) {
#pragma unroll
                for (int nf = 0; nf < 4; nf++) {
                    bool act = (nf == 0) ? act0 : (nf == 1) ? act1 : (nf == 2) ? act2 : act3;
                    if (act) {
                        uint32_t* bhp = &bH[nf >> 1][(nf & 1) * 2];
                        uint32_t* blp = &bL[nf >> 1][(nf & 1) * 2];
                        mma_bf16(d[mf][nf], aH[mf], bhp);
                        mma_bf16(d[mf][nf], aH[mf], blp);
                        mma_bf16(d[mf][nf], aL[mf], bhp);
                    }
                }
            }
        }
        if (cc + 1 < NC) store_smem(buf ^ 1);
        __syncthreads();
    }

    // epilogue
    int rbase = lane >> 2, cpair = (lane & 3) * 2;
    float bv[4][2];
#pragma unroll
    for (int nf = 0; nf < 4; nf++) {
        int c = n0 + wn * 32 + nf * 8 + cpair;
        bv[nf][0] = (bias != nullptr && c < NB) ? bias[c] : 0.f;
        bv[nf][1] = (bias != nullptr && c + 1 < NB) ? bias[c + 1] : 0.f;
    }
#pragma unroll
    for (int mf = 0; mf < 2; mf++) {
#pragma unroll
        for (int h = 0; h < 2; h++) {
            int m = m0 + wm * 32 + mf * 16 + h * 8 + rbase;
            if (m >= M) continue;
#pragma unroll
            for (int nf = 0; nf < 4; nf++) {
                int c = n0 + wn * 32 + nf * 8 + cpair;
                float v0 = d[mf][nf][h * 2 + 0] + bv[nf][0];
                float v1 = d[mf][nf][h * 2 + 1] + bv[nf][1];
                if (HAS_EPI) { v0 = elu_f(v0); v1 = elu_f(v1); }
                if (OUT_SPLIT) {
                    if (c < ldo) {
                        __nv_bfloat16 h0 = __float2bfloat16(v0);
                        __nv_bfloat16 h1v = __float2bfloat16(v1);
                        __nv_bfloat16 l0 = __float2bfloat16(v0 - __bfloat162float(h0));
                        __nv_bfloat16 l1 = __float2bfloat16(v1 - __bfloat162float(h1v));
                        *(ushort2*)&Oh[(size_t)m * ldo + c] =
                            make_ushort2(__bfloat16_as_ushort(h0), __bfloat16_as_ushort(h1v));
                        *(ushort2*)&Ol[(size_t)m * ldo + c] =
                            make_ushort2(__bfloat16_as_ushort(l0), __bfloat16_as_ushort(l1));
                    }
                } else {
                    if (c < ldo)
                        *(float2*)&Of[(size_t)m * ldo + c] = make_float2(v0, v1);
                }
            }
        }
    }
}

// ---------------- launch ----------------
extern "C" void kernel_launch(void* const* d_in, const int* in_sizes, int n_in,
                              void* d_out, int out_size) {
    const float* x   = (const float*)d_in[0];
    const int*   src = (const int*)d_in[1];
    const int*   dst = (const int*)d_in[2];
    const float* W1  = (const float*)d_in[3];
    const float* b1  = (const float*)d_in[4];
    const float* Wn  = (const float*)d_in[5];
    const float* Ws  = (const float*)d_in[6];
    const float* b2  = (const float*)d_in[7];
    const float* W3  = (const float*)d_in[8];
    const float* b3  = (const float*)d_in[9];
    float* out = (float*)d_out;

    auto sym = [](const void* s) { void* p = nullptr; cudaGetSymbolAddress(&p, s); return p; };
    __nv_bfloat16* aggh = (__nv_bfloat16*)sym(g_aggh);
    __nv_bfloat16* aggl = (__nv_bfloat16*)sym(g_aggl);
    __nv_bfloat16* h1h  = (__nv_bfloat16*)sym(g_h1h);
    __nv_bfloat16* h1l  = (__nv_bfloat16*)sym(g_h1l);
    __nv_bfloat16* h2h  = (__nv_bfloat16*)sym(g_h2h);
    __nv_bfloat16* h2l  = (__nv_bfloat16*)sym(g_h2l);
    float* hWn   = (float*)sym(g_hWn);
    float* h2pre = (float*)sym(g_h2pre);
    __nv_bfloat16* B1h  = (__nv_bfloat16*)sym(g_B1h),  *B1l  = (__nv_bfloat16*)sym(g_B1l);
    __nv_bfloat16* BWnh = (__nv_bfloat16*)sym(g_BWnh), *BWnl = (__nv_bfloat16*)sym(g_BWnl);
    __nv_bfloat16* BWsh = (__nv_bfloat16*)sym(g_BWsh), *BWsl = (__nv_bfloat16*)sym(g_BWsl);
    __nv_bfloat16* B3h  = (__nv_bfloat16*)sym(g_B3h),  *B3l  = (__nv_bfloat16*)sym(g_B3l);

    const int SMEMSZ = 61440;
    cudaFuncSetAttribute(k_mm<128, true,  true >, cudaFuncAttributeMaxDynamicSharedMemorySize, SMEMSZ);
    cudaFuncSetAttribute(k_mm<160, false, false>, cudaFuncAttributeMaxDynamicSharedMemorySize, SMEMSZ);
    cudaFuncSetAttribute(k_mm<128, true,  false>, cudaFuncAttributeMaxDynamicSharedMemorySize, SMEMSZ);

    const int WPT = 192 * 128 + 128 * 160 * 2 + 64 * 128;  // 96768 > NN
    k_zero_wprep<<<(WPT + 255) / 256, 256>>>(W1, Wn, Ws, W3);
    k_degrees<<<(EE / 4 + 255) / 256, 256>>>((const int4*)src, (const int4*)dst);
    k_scan_norms<<<SCAN_B, 1024>>>();
    k_fill<<<(EE + 255) / 256, 256>>>(src, dst);

    int agg_blocks = (NN * 32 + 255) / 256;
    k_agg1<<<agg_blocks, 256>>>(x);

    int MT = (NN + 127) / 128;  // 391

    // h1 = elu(agg @ W1 + b1) -> bf16 hi/lo [NN, 160]; 3x(128x64) tiles
    k_mm<128, true, true><<<dim3(3, MT), 256, SMEMSZ>>>(
        aggh, aggl, NN, B1h, B1l, b1, D1,
        nullptr, h1h, h1l, KP1);

    // merged z-launch: hWn = h1 @ Wn (no bias); h2pre = h1 @ Ws + b2
    k_mm<160, false, false><<<dim3(2, MT), 256, SMEMSZ>>>(
        h1h, h1l, NN, BWnh, BWnl, nullptr, D2,
        hWn, nullptr, nullptr, LD2);
    k_mm<160, false, false><<<dim3(2, MT), 256, SMEMSZ>>>(
        h1h, h1l, NN, BWsh, BWsl, b2, D2,
        h2pre, nullptr, nullptr, LD2);

    // h2 = elu(h2pre + mean-agg(hWn)) -> bf16 hi/lo [NN, 128]
    k_agg2p<<<agg_blocks, 256>>>();

    // out = elu(h2 @ W3 + b3) -> fp32 [NN, 64]
    k_mm<128, true, false><<<dim3(1, MT), 256, SMEMSZ>>>(
        h2h, h2l, NN, B3h, B3l, b3, DOUT,
        out, nullptr, nullptr, DOUT);
}

// round 15
// speedup vs baseline: 1.8102x; 1.1521x over previous
#include <cuda_runtime.h>
#include <cuda_bf16.h>
#include <math.h>
#include <stdint.h>

#define NN   50000
#define EE   800000
#define DIN  128
#define D1   150
#define KP1  160     // h1 K-padded (row stride)
#define D2   100
#define LD2  100     // fp32 hWn/h2pre stride
#define KP2  128     // h2 K-padded
#define DOUT 64
#define CAP  64      // bucketed-CSR capacity (Poisson(16): P(deg>64) ~ 1e-20)

// ---------------- scratch ----------------
__device__ int   g_cnt[NN];                 // in-degree counter / bucket cursor
__device__ float g_deg_out[NN];
__device__ float g_norm_out[NN];
__device__ int   g_csr[(size_t)NN * CAP];   // bucketed CSR, 12.8MB

__device__ __align__(16) __nv_bfloat16 g_aggh[(size_t)NN * DIN];
__device__ __align__(16) __nv_bfloat16 g_aggl[(size_t)NN * DIN];
__device__ __align__(16) __nv_bfloat16 g_h1h[(size_t)NN * KP1];
__device__ __align__(16) __nv_bfloat16 g_h1l[(size_t)NN * KP1];
__device__ __align__(16) __nv_bfloat16 g_h2h[(size_t)NN * KP2];
__device__ __align__(16) __nv_bfloat16 g_h2l[(size_t)NN * KP2];
__device__ __align__(16) float g_hWn[(size_t)NN * LD2];
__device__ __align__(16) float g_h2pre[(size_t)NN * LD2];

// weights transposed [NPAD, KPAD] bf16 hi/lo
__device__ __align__(16) __nv_bfloat16 g_B1h[192 * 128],  g_B1l[192 * 128];
__device__ __align__(16) __nv_bfloat16 g_BWmh[256 * 160], g_BWml[256 * 160]; // [Wn|Ws]
__device__ __align__(16) __nv_bfloat16 g_B3h[64 * 128],   g_B3l[64 * 128];
__device__ float g_bias_m[256];  // [0.. , b2.. , 0..]

// fast ELU (MUFU-based)
__device__ __forceinline__ float elu_f(float v) {
    return v > 0.f ? v : (__expf(v) - 1.f);
}

__device__ __forceinline__ uint32_t smem_u32(const void* p) {
    uint32_t a;
    asm("{ .reg .u64 t; cvta.to.shared.u64 t, %1; cvt.u32.u64 %0, t; }" : "=r"(a) : "l"(p));
    return a;
}
__device__ __forceinline__ void ldsm_x4(uint32_t addr, uint32_t* r) {
    asm volatile("ldmatrix.sync.aligned.m8n8.x4.shared.b16 {%0,%1,%2,%3}, [%4];"
                 : "=r"(r[0]), "=r"(r[1]), "=r"(r[2]), "=r"(r[3]) : "r"(addr));
}
__device__ __forceinline__ void mma_bf16(float* d, const uint32_t* a, const uint32_t* b) {
    asm volatile("mma.sync.aligned.m16n8k16.row.col.f32.bf16.bf16.f32 "
                 "{%0,%1,%2,%3}, {%4,%5,%6,%7}, {%8,%9}, {%0,%1,%2,%3};"
                 : "+f"(d[0]), "+f"(d[1]), "+f"(d[2]), "+f"(d[3])
                 : "r"(a[0]), "r"(a[1]), "r"(a[2]), "r"(a[3]), "r"(b[0]), "r"(b[1]));
}

// ---------------- weight split helper ----------------
__device__ __forceinline__ void wsplit(const float* W, int KB, int NB, int KPAD,
                                       __nv_bfloat16* bh, __nv_bfloat16* bl, int idx) {
    int n = idx / KPAD, k = idx % KPAD;
    float v = (n < NB && k < KB) ? W[(size_t)k * NB + n] : 0.f;
    __nv_bfloat16 hv = __float2bfloat16(v);
    bh[idx] = hv;
    bl[idx] = __float2bfloat16(v - __bfloat162float(hv));
}

// ---------------- merged zero + weight prep ----------------
__global__ void k_zero_wprep(const float* __restrict__ W1, const float* __restrict__ Wn,
                             const float* __restrict__ Ws, const float* __restrict__ W3,
                             const float* __restrict__ b2) {
    int i = blockIdx.x * 256 + threadIdx.x;
    if (i < NN) { g_cnt[i] = 0; g_deg_out[i] = 0.f; }
    const int S1 = 192 * 128, S2 = 256 * 160, S4 = 64 * 128;
    if (i < S1) { wsplit(W1, DIN, D1, 128, g_B1h, g_B1l, i); return; }
    i -= S1;
    if (i < S2) {  // merged [Wn rows 0..99 | Ws rows 100..199 | zeros]
        int n = i / 160, k = i % 160;
        float v = 0.f;
        if (n < 100 && k < D1)                   v = Wn[(size_t)k * D2 + n];
        else if (n >= 100 && n < 200 && k < D1)  v = Ws[(size_t)k * D2 + (n - 100)];
        __nv_bfloat16 hv = __float2bfloat16(v);
        g_BWmh[i] = hv;
        g_BWml[i] = __float2bfloat16(v - __bfloat162float(hv));
        return;
    }
    i -= S2;
    if (i < S4) { wsplit(W3, D2, DOUT, 128, g_B3h, g_B3l, i); return; }
    i -= S4;
    if (i < 256) g_bias_m[i] = (i >= 100 && i < 200) ? b2[i - 100] : 0.f;
}

// ---------------- one-pass CSR build + out-degree (no scan needed) ----------------
__global__ void k_fill2(const int* __restrict__ src, const int* __restrict__ dst) {
    int e = blockIdx.x * blockDim.x + threadIdx.x;
    if (e >= EE) return;
    int s = src[e], d = dst[e];
    int p = atomicAdd(&g_cnt[d], 1);
    if (p < CAP) g_csr[(size_t)d * CAP + p] = s;
    atomicAdd(&g_deg_out[s], 1.f);
}

__global__ void k_norms() {
    int i = blockIdx.x * blockDim.x + threadIdx.x;
    if (i < NN) g_norm_out[i] = rsqrtf(fmaxf(g_deg_out[i], 1.f));
}

// ---------------- layer-1 aggregation -> bf16 hi/lo ----------------
__global__ void k_agg1(const float* __restrict__ x) {
    int w    = (blockIdx.x * blockDim.x + threadIdx.x) >> 5;
    int lane = threadIdx.x & 31;
    if (w >= NN) return;
    int cnt = g_cnt[w];
    int deg = min(cnt, CAP);
    const int* row = g_csr + (size_t)w * CAP;
    const float4* X = (const float4*)x;
    float4 acc = make_float4(0.f, 0.f, 0.f, 0.f);
    int j = 0;
    for (; j + 3 < deg; j += 4) {
        int s0 = row[j], s1 = row[j + 1], s2 = row[j + 2], s3 = row[j + 3];
        float w0 = g_norm_out[s0], w1 = g_norm_out[s1];
        float w2 = g_norm_out[s2], w3 = g_norm_out[s3];
        float4 v0 = X[(size_t)s0 * 32 + lane];
        float4 v1 = X[(size_t)s1 * 32 + lane];
        float4 v2 = X[(size_t)s2 * 32 + lane];
        float4 v3 = X[(size_t)s3 * 32 + lane];
        acc.x += v0.x * w0 + v1.x * w1 + v2.x * w2 + v3.x * w3;
        acc.y += v0.y * w0 + v1.y * w1 + v2.y * w2 + v3.y * w3;
        acc.z += v0.z * w0 + v1.z * w1 + v2.z * w2 + v3.z * w3;
        acc.w += v0.w * w0 + v1.w * w1 + v2.w * w2 + v3.w * w3;
    }
    for (; j < deg; j++) {
        int s0 = row[j];
        float w0 = g_norm_out[s0];
        float4 v0 = X[(size_t)s0 * 32 + lane];
        acc.x += v0.x * w0; acc.y += v0.y * w0; acc.z += v0.z * w0; acc.w += v0.w * w0;
    }
    float ni = rsqrtf(fmaxf((float)cnt, 1.f));
    float v[4] = { acc.x * ni, acc.y * ni, acc.z * ni, acc.w * ni };
    __nv_bfloat16 hv[4], lv[4];
#pragma unroll
    for (int q = 0; q < 4; q++) {
        hv[q] = __float2bfloat16(v[q]);
        lv[q] = __float2bfloat16(v[q] - __bfloat162float(hv[q]));
    }
    *(ushort4*)&g_aggh[(size_t)w * DIN + lane * 4] =
        make_ushort4(__bfloat16_as_ushort(hv[0]), __bfloat16_as_ushort(hv[1]),
                     __bfloat16_as_ushort(hv[2]), __bfloat16_as_ushort(hv[3]));
    *(ushort4*)&g_aggl[(size_t)w * DIN + lane * 4] =
        make_ushort4(__bfloat16_as_ushort(lv[0]), __bfloat16_as_ushort(lv[1]),
                     __bfloat16_as_ushort(lv[2]), __bfloat16_as_ushort(lv[3]));
}

// ---- fused SAGE tail: h2 = elu(h2pre + mean-agg(hWn)) -> bf16 hi/lo [NN,128] ----
__global__ void k_agg2p() {
    int w    = (blockIdx.x * blockDim.x + threadIdx.x) >> 5;
    int lane = threadIdx.x & 31;
    if (w >= NN) return;
    int cnt = g_cnt[w];
    float4 acc = make_float4(0.f, 0.f, 0.f, 0.f);
    if (lane < LD2 / 4) {
        int deg = min(cnt, CAP);
        const int* row = g_csr + (size_t)w * CAP;
        const float4* X = (const float4*)g_hWn;
        int j = 0;
        for (; j + 1 < deg; j += 2) {
            int s0 = row[j], s1 = row[j + 1];
            float4 v0 = X[(size_t)s0 * (LD2 / 4) + lane];
            float4 v1 = X[(size_t)s1 * (LD2 / 4) + lane];
            acc.x += v0.x + v1.x; acc.y += v0.y + v1.y;
            acc.z += v0.z + v1.z; acc.w += v0.w + v1.w;
        }
        if (j < deg) {
            int s0 = row[j];
            float4 v0 = X[(size_t)s0 * (LD2 / 4) + lane];
            acc.x += v0.x; acc.y += v0.y; acc.z += v0.z; acc.w += v0.w;
        }
        float inv = 1.f / fmaxf((float)cnt, 1.f);
        float4 p = ((const float4*)g_h2pre)[(size_t)w * (LD2 / 4) + lane];
        acc.x = elu_f(p.x + acc.x * inv);
        acc.y = elu_f(p.y + acc.y * inv);
        acc.z = elu_f(p.z + acc.z * inv);
        acc.w = elu_f(p.w + acc.w * inv);
    }
    float v[4] = { acc.x, acc.y, acc.z, acc.w };
    __nv_bfloat16 hv[4], lv[4];
#pragma unroll
    for (int q = 0; q < 4; q++) {
        hv[q] = __float2bfloat16(v[q]);
        lv[q] = __float2bfloat16(v[q] - __bfloat162float(hv[q]));
    }
    *(ushort4*)&g_h2h[(size_t)w * KP2 + lane * 4] =
        make_ushort4(__bfloat16_as_ushort(hv[0]), __bfloat16_as_ushort(hv[1]),
                     __bfloat16_as_ushort(hv[2]), __bfloat16_as_ushort(hv[3]));
    *(ushort4*)&g_h2l[(size_t)w * KP2 + lane * 4] =
        make_ushort4(__bfloat16_as_ushort(lv[0]), __bfloat16_as_ushort(lv[1]),
                     __bfloat16_as_ushort(lv[2]), __bfloat16_as_ushort(lv[3]));
}

// ---------------- fused 3-term bf16-split GEMM, double-buffered ----------------
// OUTM: 0 = fp32 single, 1 = bf16 hi/lo split, 2 = dual fp32 (c<100->Of, else Og)
template<int KPAD, int OUTM, bool HAS_EPI>
__global__ void __launch_bounds__(256, 2) k_mm(
    const __nv_bfloat16* __restrict__ Ah, const __nv_bfloat16* __restrict__ Al,
    int M,
    const __nv_bfloat16* __restrict__ Bh, const __nv_bfloat16* __restrict__ Bl,
    const float* __restrict__ bias, int NB,
    float* __restrict__ Of, float* __restrict__ Og,
    __nv_bfloat16* __restrict__ Oh, __nv_bfloat16* __restrict__ Ol, int ldo)
{
    constexpr int NT  = 64;
    constexpr int NC  = KPAD / 32;
    constexpr int ATB = 128 * 80;
    constexpr int BTB = NT * 80;
    extern __shared__ __align__(16) char smem[];
    const int O_AL = 2 * ATB;
    const int O_BH = 4 * ATB;
    const int O_BL = 4 * ATB + 2 * BTB;

    int t = threadIdx.x, lane = t & 31, wid = t >> 5;
    int wm = wid & 3, wn = wid >> 2;
    int m0 = blockIdx.y * 128, n0 = blockIdx.x * NT;

    int cw = n0 + wn * 32;
    bool act0 = (cw + 0)  < NB;
    bool act1 = (cw + 8)  < NB;
    bool act2 = (cw + 16) < NB;
    bool act3 = (cw + 24) < NB;
    bool act23 = act2 | act3;

    uint32_t sbase = smem_u32(smem);
    int tile = lane >> 3, trow = lane & 7;
    uint32_t aOff = (uint32_t)(((wm * 32 + (tile & 1) * 8 + trow) * 40 + (tile >> 1) * 8) * 2);
    uint32_t bOff = (uint32_t)(((wn * 32 + (tile >> 1) * 8 + trow) * 40 + (tile & 1) * 8) * 2);

    float d[2][4][4];
#pragma unroll
    for (int i = 0; i < 2; i++)
#pragma unroll
        for (int j = 0; j < 4; j++)
#pragma unroll
            for (int q = 0; q < 4; q++) d[i][j][q] = 0.f;

    uint4 rah[2], ral[2];
    uint4 rbh, rbl, rbh2, rbl2;
    int arow = t >> 1, ahalf = t & 1, brow = t >> 1, bq = t & 1;
    int mload = m0 + arow; if (mload >= M) mload = M - 1;

    auto ldregs = [&](int cc) {
        int k0 = cc * 32;
        const char* ah = (const char*)(Ah + (size_t)mload * KPAD + k0) + ahalf * 32;
        const char* al = (const char*)(Al + (size_t)mload * KPAD + k0) + ahalf * 32;
        rah[0] = *(const uint4*)ah;  rah[1] = *(const uint4*)(ah + 16);
        ral[0] = *(const uint4*)al;  ral[1] = *(const uint4*)(al + 16);
        if (t < NT * 2) {
            int n = n0 + brow;
            const char* bh = (const char*)(Bh + (size_t)n * KPAD + k0) + bq * 32;
            const char* bl = (const char*)(Bl + (size_t)n * KPAD + k0) + bq * 32;
            rbh  = *(const uint4*)bh;  rbh2 = *(const uint4*)(bh + 16);
            rbl  = *(const uint4*)bl;  rbl2 = *(const uint4*)(bl + 16);
        }
    };
    auto store_smem = [&](int buf) {
        char* pah = smem + buf * ATB + arow * 80 + ahalf * 32;
        char* pal = smem + O_AL + buf * ATB + arow * 80 + ahalf * 32;
        *(uint4*)pah = rah[0]; *(uint4*)(pah + 16) = rah[1];
        *(uint4*)pal = ral[0]; *(uint4*)(pal + 16) = ral[1];
        if (t < NT * 2) {
            char* pbh = smem + O_BH + buf * BTB + brow * 80 + bq * 32;
            char* pbl = smem + O_BL + buf * BTB + brow * 80 + bq * 32;
            *(uint4*)pbh = rbh; *(uint4*)(pbh + 16) = rbh2;
            *(uint4*)pbl = rbl; *(uint4*)(pbl + 16) = rbl2;
        }
    };

    ldregs(0);
    store_smem(0);
    __syncthreads();
#pragma unroll 1
    for (int cc = 0; cc < NC; cc++) {
        int buf = cc & 1;
        if (cc + 1 < NC) ldregs(cc + 1);
        uint32_t aH_addr = sbase + buf * ATB + aOff;
        uint32_t aL_addr = sbase + O_AL + buf * ATB + aOff;
        uint32_t bH_addr = sbase + O_BH + buf * BTB + bOff;
        uint32_t bL_addr = sbase + O_BL + buf * BTB + bOff;
#pragma unroll
        for (int kk = 0; kk < 2; kk++) {
            uint32_t aH[2][4], aL[2][4], bH[2][4], bL[2][4];
            ldsm_x4(aH_addr + kk * 32, aH[0]);
            ldsm_x4(aH_addr + 1280 + kk * 32, aH[1]);
            ldsm_x4(aL_addr + kk * 32, aL[0]);
            ldsm_x4(aL_addr + 1280 + kk * 32, aL[1]);
            ldsm_x4(bH_addr + kk * 32, bH[0]);
            ldsm_x4(bL_addr + kk * 32, bL[0]);
            if (act23) {
                ldsm_x4(bH_addr + 1280 + kk * 32, bH[1]);
                ldsm_x4(bL_addr + 1280 + kk * 32, bL[1]);
            }
#pragma unroll
            for (int mf = 0; mf < 2; mf++) {
#pragma unroll
                for (int nf = 0; nf < 4; nf++) {
                    bool act = (nf == 0) ? act0 : (nf == 1) ? act1 : (nf == 2) ? act2 : act3;
                    if (act) {
                        uint32_t* bhp = &bH[nf >> 1][(nf & 1) * 2];
                        uint32_t* blp = &bL[nf >> 1][(nf & 1) * 2];
                        mma_bf16(d[mf][nf], aH[mf], bhp);
                        mma_bf16(d[mf][nf], aH[mf], blp);
                        mma_bf16(d[mf][nf], aL[mf], bhp);
                    }
                }
            }
        }
        if (cc + 1 < NC) store_smem(buf ^ 1);
        __syncthreads();
    }

    // epilogue
    int rbase = lane >> 2, cpair = (lane & 3) * 2;
    float bv[4][2];
#pragma unroll
    for (int nf = 0; nf < 4; nf++) {
        int c = n0 + wn * 32 + nf * 8 + cpair;
        bv[nf][0] = (bias != nullptr && c < NB) ? bias[c] : 0.f;
        bv[nf][1] = (bias != nullptr && c + 1 < NB) ? bias[c + 1] : 0.f;
    }
#pragma unroll
    for (int mf = 0; mf < 2; mf++) {
#pragma unroll
        for (int h = 0; h < 2; h++) {
            int m = m0 + wm * 32 + mf * 16 + h * 8 + rbase;
            if (m >= M) continue;
#pragma unroll
            for (int nf = 0; nf < 4; nf++) {
                int c = n0 + wn * 32 + nf * 8 + cpair;
                float v0 = d[mf][nf][h * 2 + 0] + bv[nf][0];
                float v1 = d[mf][nf][h * 2 + 1] + bv[nf][1];
                if (HAS_EPI) { v0 = elu_f(v0); v1 = elu_f(v1); }
                if (OUTM == 1) {
                    if (c < ldo) {
                        __nv_bfloat16 h0 = __float2bfloat16(v0);
                        __nv_bfloat16 h1v = __float2bfloat16(v1);
                        __nv_bfloat16 l0 = __float2bfloat16(v0 - __bfloat162float(h0));
                        __nv_bfloat16 l1 = __float2bfloat16(v1 - __bfloat162float(h1v));
                        *(ushort2*)&Oh[(size_t)m * ldo + c] =
                            make_ushort2(__bfloat16_as_ushort(h0), __bfloat16_as_ushort(h1v));
                        *(ushort2*)&Ol[(size_t)m * ldo + c] =
                            make_ushort2(__bfloat16_as_ushort(l0), __bfloat16_as_ushort(l1));
                    }
                } else if (OUTM == 0) {
                    if (c < ldo)
                        *(float2*)&Of[(size_t)m * ldo + c] = make_float2(v0, v1);
                } else {  // dual fp32: regions 100-aligned, pairs never straddle
                    if (c < 100)
                        *(float2*)&Of[(size_t)m * 100 + c] = make_float2(v0, v1);
                    else if (c < NB)
                        *(float2*)&Og[(size_t)m * 100 + (c - 100)] = make_float2(v0, v1);
                }
            }
        }
    }
}

// ---------------- launch ----------------
extern "C" void kernel_launch(void* const* d_in, const int* in_sizes, int n_in,
                              void* d_out, int out_size) {
    const float* x   = (const float*)d_in[0];
    const int*   src = (const int*)d_in[1];
    const int*   dst = (const int*)d_in[2];
    const float* W1  = (const float*)d_in[3];
    const float* b1  = (const float*)d_in[4];
    const float* Wn  = (const float*)d_in[5];
    const float* Ws  = (const float*)d_in[6];
    const float* b2  = (const float*)d_in[7];
    const float* W3  = (const float*)d_in[8];
    const float* b3  = (const float*)d_in[9];
    float* out = (float*)d_out;

    auto sym = [](const void* s) { void* p = nullptr; cudaGetSymbolAddress(&p, s); return p; };
    __nv_bfloat16* aggh = (__nv_bfloat16*)sym(g_aggh);
    __nv_bfloat16* aggl = (__nv_bfloat16*)sym(g_aggl);
    __nv_bfloat16* h1h  = (__nv_bfloat16*)sym(g_h1h);
    __nv_bfloat16* h1l  = (__nv_bfloat16*)sym(g_h1l);
    __nv_bfloat16* h2h  = (__nv_bfloat16*)sym(g_h2h);
    __nv_bfloat16* h2l  = (__nv_bfloat16*)sym(g_h2l);
    float* hWn   = (float*)sym(g_hWn);
    float* h2pre = (float*)sym(g_h2pre);
    float* biasm = (float*)sym(g_bias_m);
    __nv_bfloat16* B1h  = (__nv_bfloat16*)sym(g_B1h),  *B1l  = (__nv_bfloat16*)sym(g_B1l);
    __nv_bfloat16* BWmh = (__nv_bfloat16*)sym(g_BWmh), *BWml = (__nv_bfloat16*)sym(g_BWml);
    __nv_bfloat16* B3h  = (__nv_bfloat16*)sym(g_B3h),  *B3l  = (__nv_bfloat16*)sym(g_B3l);

    const int SMEMSZ = 61440;
    cudaFuncSetAttribute(k_mm<128, 1, true >, cudaFuncAttributeMaxDynamicSharedMemorySize, SMEMSZ);
    cudaFuncSetAttribute(k_mm<160, 2, false>, cudaFuncAttributeMaxDynamicSharedMemorySize, SMEMSZ);
    cudaFuncSetAttribute(k_mm<128, 0, true >, cudaFuncAttributeMaxDynamicSharedMemorySize, SMEMSZ);

    const int WPT = 192 * 128 + 256 * 160 + 64 * 128 + 256;  // 73984 > NN
    k_zero_wprep<<<(WPT + 255) / 256, 256>>>(W1, Wn, Ws, W3, b2);
    k_fill2<<<(EE + 255) / 256, 256>>>(src, dst);
    k_norms<<<(NN + 255) / 256, 256>>>();

    int agg_blocks = (NN * 32 + 255) / 256;
    k_agg1<<<agg_blocks, 256>>>(x);

    int MT = (NN + 127) / 128;  // 391

    // h1 = elu(agg @ W1 + b1) -> bf16 hi/lo [NN, 160]
    k_mm<128, 1, true><<<dim3(3, MT), 256, SMEMSZ>>>(
        aggh, aggl, NN, B1h, B1l, b1, D1,
        nullptr, nullptr, h1h, h1l, KP1);

    // [hWn | h2pre] = h1 @ [Wn | Ws] + [0 | b2]  (one launch, dual fp32 out)
    k_mm<160, 2, false><<<dim3(4, MT), 256, SMEMSZ>>>(
        h1h, h1l, NN, BWmh, BWml, biasm, 200,
        hWn, h2pre, nullptr, nullptr, LD2);

    // h2 = elu(h2pre + mean-agg(hWn)) -> bf16 hi/lo [NN, 128]
    k_agg2p<<<agg_blocks, 256>>>();

    // out = elu(h2 @ W3 + b3) -> fp32 [NN, 64]
    k_mm<128, 0, true><<<dim3(1, MT), 256, SMEMSZ>>>(
        h2h, h2l, NN, B3h, B3l, b3, DOUT,
        out, nullptr, nullptr, nullptr, DOUT);
}